// round 11
// baseline (speedup 1.0000x reference)
#include <cuda_runtime.h>
#include <cuda_bf16.h>
#include <cuda_fp16.h>
#include <math.h>
#include <stdint.h>

#define BT 2
#define CC 128
#define HH 128
#define WW 128
#define HS 64
#define NP 4096
#define K1 1152
#define HWF 16384
#define SCALEF 10.0f
#define SEL_THR 1e-7f
#define SLOTS 16
#define KMAX 128
#define CHUNKS 64

// ===================== scratch =====================
__device__ __align__(256) __nv_bfloat16 g_bh [(size_t)BT*NP*CC];
__device__ __align__(256) __nv_bfloat16 g_bl [(size_t)BT*NP*CC];
__device__ __align__(256) __nv_bfloat16 g_fh [(size_t)BT*NP*CC];
__device__ __align__(256) __nv_bfloat16 g_fl [(size_t)BT*NP*CC];
__device__ __align__(256) __half        g_bgcl[(size_t)BT*HWF*CC];
__device__ __align__(256) __half        g_y16 [(size_t)BT*HWF*CC];
__device__ __align__(256) __half        g_h16 [(size_t)BT*HWF*CC];
__device__ __align__(256) __half        g_w1h16[CC*K1], g_w1l16[CC*K1];
__device__ __align__(256) __half        g_w2h16[CC*K1], g_w2l16[CC*K1];
__device__ __align__(256) float g_bufA[(size_t)BT*NP*NP];
__device__ __align__(256) float g_bufB[(size_t)BT*NP*NP];
__device__ int   g_cidx[(size_t)BT*NP*CHUNKS*SLOTS];
__device__ float g_cwgt[(size_t)BT*NP*CHUNKS*SLOTS];
__device__ int   g_ccnt[BT*NP*CHUNKS];
__device__ int   g_midx[(size_t)BT*NP*KMAX];
__device__ float g_mwgt[(size_t)BT*NP*KMAX];
__device__ int   g_mcnt[BT*NP];
__device__ float g_eq  [NP];
__device__ float g_ss  [BT*NP];
__device__ float g_inv [BT*NP];
__device__ float g_pmax[(size_t)BT*CHUNKS*NP];
__device__ float g_psum[(size_t)BT*CHUNKS*NP];
__device__ float g_cmax[BT*NP];
__device__ float g_csum[BT*NP];
__device__ float g_lthr[BT*NP];

__device__ __forceinline__ void split_store(__nv_bfloat16* H, __nv_bfloat16* L,
                                            size_t idx, float v) {
    __nv_bfloat16 h = __float2bfloat16(v);
    H[idx] = h;
    L[idx] = __float2bfloat16(v - __bfloat162float(h));
}
__device__ __forceinline__ void split_store16(__half* H, __half* L, size_t idx, float v) {
    __half h = __float2half(v);
    H[idx] = h;
    L[idx] = __float2half(v - __half2float(h));
}
__device__ __forceinline__ uint32_t smem_u32(const void* p) {
    uint32_t a;
    asm("{ .reg .u64 t; cvta.to.shared.u64 t, %1; cvt.u32.u64 %0, t; }" : "=r"(a) : "l"(p));
    return a;
}
__device__ __forceinline__ void ldsm_x4(uint32_t (&r)[4], uint32_t addr) {
    asm volatile("ldmatrix.sync.aligned.m8n8.x4.shared.b16 {%0,%1,%2,%3}, [%4];"
                 : "=r"(r[0]), "=r"(r[1]), "=r"(r[2]), "=r"(r[3]) : "r"(addr));
}
__device__ __forceinline__ void mma_bf16(float (&d)[4], const uint32_t (&a)[4],
                                         uint32_t b0, uint32_t b1) {
    asm volatile("mma.sync.aligned.m16n8k16.row.col.f32.bf16.bf16.f32 "
        "{%0,%1,%2,%3}, {%4,%5,%6,%7}, {%8,%9}, {%0,%1,%2,%3};"
        : "+f"(d[0]), "+f"(d[1]), "+f"(d[2]), "+f"(d[3])
        : "r"(a[0]), "r"(a[1]), "r"(a[2]), "r"(a[3]), "r"(b0), "r"(b1));
}
__device__ __forceinline__ void mma_f16(float (&d)[4], const uint32_t (&a)[4],
                                        uint32_t b0, uint32_t b1) {
    asm volatile("mma.sync.aligned.m16n8k16.row.col.f32.f16.f16.f32 "
        "{%0,%1,%2,%3}, {%4,%5,%6,%7}, {%8,%9}, {%0,%1,%2,%3};"
        : "+f"(d[0]), "+f"(d[1]), "+f"(d[2]), "+f"(d[3])
        : "r"(a[0]), "r"(a[1]), "r"(a[2]), "r"(a[3]), "r"(b0), "r"(b1));
}
__device__ __forceinline__ void cpasync16(uint32_t saddr, const void* g) {
    asm volatile("cp.async.cg.shared.global [%0], [%1], 16;" :: "r"(saddr), "l"(g));
}
__device__ __forceinline__ void cpasync16z(uint32_t saddr, const void* g, int szbytes) {
    asm volatile("cp.async.cg.shared.global [%0], [%1], 16, %2;"
                 :: "r"(saddr), "l"(g), "r"(szbytes));
}

// ===================== prep =====================
__global__ void k_half(const float* __restrict__ src, __nv_bfloat16* H, __nv_bfloat16* L) {
    int idx = blockIdx.x * blockDim.x + threadIdx.x;
    if (idx >= BT * NP * CC) return;
    int c = idx & 127;
    int t = idx >> 7;
    int n = t & 4095;
    int b = t >> 12;
    int y = n >> 6, x = n & 63;
    float v = src[(((size_t)b*CC + c)*HH + 2*y)*WW + 2*x];
    split_store(H, L, (size_t)idx, v);
}

__global__ void k_ss() {
    int idx = blockIdx.x * blockDim.x + threadIdx.x;
    if (idx >= BT * NP) return;
    const __nv_bfloat162* h2 = (const __nv_bfloat162*)(g_bh + (size_t)idx * CC);
    const __nv_bfloat162* l2 = (const __nv_bfloat162*)(g_bl + (size_t)idx * CC);
    float s = 0.f;
#pragma unroll
    for (int c = 0; c < CC/2; c++) {
        float2 a = __bfloat1622float2(h2[c]);
        float2 bb = __bfloat1622float2(l2[c]);
        float v0 = a.x + bb.x, v1 = a.y + bb.y;
        s += v0*v0 + v1*v1;
    }
    g_ss[idx] = s;
}

__global__ void k_inv() {
    int idx = blockIdx.x * blockDim.x + threadIdx.x;
    if (idx >= BT * NP) return;
    int b = idx >> 12, n = idx & 4095;
    int ny = n >> 6, nx = n & 63;
    float s = 0.f;
#pragma unroll
    for (int i = 0; i < 3; i++)
#pragma unroll
        for (int j = 0; j < 3; j++) {
            int y = ny + i - 1, x = nx + j - 1;
            if ((unsigned)y < 64u && (unsigned)x < 64u)
                s += g_ss[b*NP + y*64 + x];
        }
    g_inv[idx] = 1.f / fmaxf(sqrtf(s), 1e-4f);
}

__global__ void k_bgcl(const float* __restrict__ bg) {
    __shared__ float tile[32][33];
    int b = blockIdx.z;
    int c0 = blockIdx.y * 32;
    int p0 = blockIdx.x * 32;
    int tx = threadIdx.x & 31, ty = threadIdx.x >> 5;
#pragma unroll
    for (int k = 0; k < 4; k++) {
        int c = c0 + ty + k*8;
        tile[ty + k*8][tx] = bg[((size_t)(b*CC + c))*HWF + p0 + tx];
    }
    __syncthreads();
#pragma unroll
    for (int k = 0; k < 4; k++) {
        int p = p0 + ty + k*8;
        g_bgcl[((size_t)(b*HWF + p))*CC + c0 + tx] = __float2half(tile[tx][ty + k*8]);
    }
}

__global__ void k_eq(const float* __restrict__ mask) {
    int n = blockIdx.x * blockDim.x + threadIdx.x;
    if (n >= NP) return;
    int ny = n / HS, nx = n % HS;
    float s = 0.f;
#pragma unroll
    for (int i = 0; i < 3; i++)
#pragma unroll
        for (int j = 0; j < 3; j++) {
            int y = ny + i - 1, x = nx + j - 1;
            if ((unsigned)y < HS && (unsigned)x < HS)
                s += mask[(2*y)*WW + 2*x];
        }
    g_eq[n] = ((s / 9.f) == 0.f) ? 1.f : 0.f;
}

__global__ void k_wreorder(const float* __restrict__ w, __half* H, __half* L) {
    int idx = blockIdx.x * blockDim.x + threadIdx.x;
    if (idx >= CC * K1) return;
    int r = idx / K1;
    int rem = idx % K1;
    int tap = rem >> 7;
    int c = rem & 127;
    split_store16(H, L, (size_t)idx, w[r * K1 + c * 9 + tap]);
}

// ===================== bf16-split GEMM (3-term, 128x128) — GEMM1 =============
#define KT 32
#define STAGES 3
#define STAGE_BYTES (4*128*KT*2)
#define MGEMM_SMEM (STAGES*STAGE_BYTES)

__global__ void __launch_bounds__(256, 1) mgemm(
    const __nv_bfloat16* __restrict__ Ah, const __nv_bfloat16* __restrict__ Al,
    const __nv_bfloat16* __restrict__ Bh, const __nv_bfloat16* __restrict__ Bl,
    float* __restrict__ C, int K, int N,
    size_t sA, size_t sB, size_t sC)
{
    extern __shared__ char sm[];
    const uint32_t smb = smem_u32(sm);
    const int tid = threadIdx.x;
    const int bz = blockIdx.z;
    const int bm = blockIdx.y * 128;
    const int bn = blockIdx.x * 128;
    C += sC * bz;

    const int j   = tid >> 6;
    const int l64 = tid & 63;
    const int rbase = (j < 2) ? bm : bn;
    const __nv_bfloat16* src =
        (j == 0) ? Ah + sA*bz : (j == 1) ? Al + sA*bz : (j == 2) ? Bh + sB*bz : Bl + sB*bz;

    const int NC = K >> 5;

#pragma unroll
    for (int s = 0; s < STAGES - 1; s++) {
        const int kc = s * KT;
#pragma unroll
        for (int i = 0; i < 8; i++) {
            int id = l64 + i * 64;
            int row = id >> 2, ch = id & 3;
            const void* g = src + (size_t)(rbase + row) * K + kc + ch * 8;
            uint32_t sa = smb + s*STAGE_BYTES + j*8192 + row*64 + ((ch ^ ((row >> 1) & 3)) << 4);
            cpasync16(sa, g);
        }
        asm volatile("cp.async.commit_group;");
    }

    const int wid = tid >> 5, lane = tid & 31;
    const int wm = wid & 1, wn = wid >> 1;

    float acc[4][4][4];
#pragma unroll
    for (int a = 0; a < 4; a++)
#pragma unroll
        for (int bb = 0; bb < 4; bb++)
#pragma unroll
            for (int c = 0; c < 4; c++) acc[a][bb][c] = 0.f;

    for (int i = 0; i < NC; i++) {
        asm volatile("cp.async.wait_group 1;");
        __syncthreads();

        if (i + STAGES - 1 < NC) {
            const int s2 = (i + STAGES - 1) % STAGES;
            const int kc = (i + STAGES - 1) * KT;
#pragma unroll
            for (int it = 0; it < 8; it++) {
                int id = l64 + it * 64;
                int row = id >> 2, ch = id & 3;
                const void* g = src + (size_t)(rbase + row) * K + kc + ch * 8;
                uint32_t sa = smb + s2*STAGE_BYTES + j*8192 + row*64 + ((ch ^ ((row >> 1) & 3)) << 4);
                cpasync16(sa, g);
            }
        }
        asm volatile("cp.async.commit_group;");

        const uint32_t stb = smb + (i % STAGES) * STAGE_BYTES;
#pragma unroll
        for (int h = 0; h < 2; h++) {
            uint32_t ah[4][4], al[4][4];
            uint32_t bh[4][2], bl[4][2];
#pragma unroll
            for (int tm = 0; tm < 4; tm++) {
                int row = wm*64 + tm*16 + (lane & 15);
                int ch  = 2*h + (lane >> 4);
                uint32_t ad = stb + row*64 + ((ch ^ ((row >> 1) & 3)) << 4);
                ldsm_x4(ah[tm], ad);
                ldsm_x4(al[tm], ad + 8192);
            }
#pragma unroll
            for (int tp = 0; tp < 2; tp++) {
                int row = wn*32 + tp*16 + ((lane >> 4) << 3) + (lane & 7);
                int ch  = 2*h + ((lane >> 3) & 1);
                uint32_t bd = stb + 16384 + row*64 + ((ch ^ ((row >> 1) & 3)) << 4);
                uint32_t r[4];
                ldsm_x4(r, bd);
                bh[tp*2][0] = r[0]; bh[tp*2][1] = r[1];
                bh[tp*2+1][0] = r[2]; bh[tp*2+1][1] = r[3];
                ldsm_x4(r, bd + 8192);
                bl[tp*2][0] = r[0]; bl[tp*2][1] = r[1];
                bl[tp*2+1][0] = r[2]; bl[tp*2+1][1] = r[3];
            }
#pragma unroll
            for (int tm = 0; tm < 4; tm++)
#pragma unroll
                for (int tn = 0; tn < 4; tn++) {
                    mma_bf16(acc[tm][tn], ah[tm], bh[tn][0], bh[tn][1]);
                    mma_bf16(acc[tm][tn], ah[tm], bl[tn][0], bl[tn][1]);
                    mma_bf16(acc[tm][tn], al[tm], bh[tn][0], bh[tn][1]);
                }
        }
    }

#pragma unroll
    for (int tm = 0; tm < 4; tm++) {
        int row = bm + wm*64 + tm*16 + (lane >> 2);
#pragma unroll
        for (int hf = 0; hf < 2; hf++) {
            int r = row + hf*8;
            float* dst = C + (size_t)r * N + bn + wn*32 + (lane & 3)*2;
#pragma unroll
            for (int tn = 0; tn < 4; tn++)
                *(float2*)(dst + tn*8) = make_float2(acc[tm][tn][hf*2+0], acc[tm][tn][hf*2+1]);
        }
    }
}

// ===================== implicit conv GEMM: 128ch x 256pix, fp16 2-term W =====
#define CSTAGE 32768
#define CGEMM_SMEM (STAGES*CSTAGE)
#define TPITCH 136

template<int OUT16>
__global__ void __launch_bounds__(256, 1) cgemm(
    const __half* __restrict__ Wh, const __half* __restrict__ Wl,
    const __half* __restrict__ img,
    float* __restrict__ Cout, __half* __restrict__ out16,
    const float* __restrict__ bias)
{
    extern __shared__ char sm[];
    const uint32_t smb = smem_u32(sm);
    const int tid = threadIdx.x;
    const int bz = blockIdx.z;
    const int bn = blockIdx.x * 256;
    const __half* ib = img + (size_t)bz * HWF * CC;

    const int NC = K1 >> 5;   // 36

    auto load_stage = [&](int s, int kc) {
#pragma unroll
        for (int it = 0; it < 2; it++) {
            int id = tid + it * 256;
            int row = id >> 2, ch = id & 3;
            uint32_t swz = (uint32_t)(row * 64 + ((ch ^ ((row >> 1) & 3)) << 4));
            cpasync16(smb + s*CSTAGE + swz,        Wh + (size_t)row * K1 + kc + ch * 8);
            cpasync16(smb + s*CSTAGE + 8192 + swz, Wl + (size_t)row * K1 + kc + ch * 8);
        }
        int tap = kc >> 7;
        int ki = tap / 3, kj = tap - ki * 3;
        int c0 = kc & 127;
#pragma unroll
        for (int it = 0; it < 4; it++) {
            int id = tid + it * 256;
            int row = id >> 2, ch = id & 3;
            int p = bn + row;
            int Y = (p >> 7) + ki - 1, X = (p & 127) + kj - 1;
            bool ok = (unsigned)Y < HH && (unsigned)X < WW;
            const __half* g = ok ? ib + ((size_t)(Y * WW + X)) * CC + c0 + ch * 8 : ib;
            uint32_t swz = (uint32_t)(row * 64 + ((ch ^ ((row >> 1) & 3)) << 4));
            cpasync16z(smb + s*CSTAGE + 16384 + swz, g, ok ? 16 : 0);
        }
        asm volatile("cp.async.commit_group;");
    };

#pragma unroll
    for (int s = 0; s < STAGES - 1; s++) load_stage(s, s * KT);

    const int wid = tid >> 5, lane = tid & 31;
    const int wm = wid & 1, wn = wid >> 1;

    float acc[4][8][4];
#pragma unroll
    for (int a = 0; a < 4; a++)
#pragma unroll
        for (int bb = 0; bb < 8; bb++)
#pragma unroll
            for (int c = 0; c < 4; c++) acc[a][bb][c] = 0.f;

    for (int i = 0; i < NC; i++) {
        asm volatile("cp.async.wait_group 1;");
        __syncthreads();

        if (i + STAGES - 1 < NC)
            load_stage((i + STAGES - 1) % STAGES, (i + STAGES - 1) * KT);
        else
            asm volatile("cp.async.commit_group;");

        const uint32_t stb = smb + (i % STAGES) * CSTAGE;
#pragma unroll
        for (int h = 0; h < 2; h++) {
            uint32_t ah[4][4], al[4][4];
            uint32_t bf[8][2];
#pragma unroll
            for (int tm = 0; tm < 4; tm++) {
                int row = wm*64 + tm*16 + (lane & 15);
                int ch  = 2*h + (lane >> 4);
                uint32_t ad = stb + row*64 + ((ch ^ ((row >> 1) & 3)) << 4);
                ldsm_x4(ah[tm], ad);
                ldsm_x4(al[tm], ad + 8192);
            }
#pragma unroll
            for (int tb = 0; tb < 4; tb++) {
                int row = wn*64 + tb*16 + ((lane >> 4) << 3) + (lane & 7);
                int ch  = 2*h + ((lane >> 3) & 1);
                uint32_t bd = stb + 16384 + row*64 + ((ch ^ ((row >> 1) & 3)) << 4);
                uint32_t r[4];
                ldsm_x4(r, bd);
                bf[tb*2][0] = r[0]; bf[tb*2][1] = r[1];
                bf[tb*2+1][0] = r[2]; bf[tb*2+1][1] = r[3];
            }
#pragma unroll
            for (int tm = 0; tm < 4; tm++)
#pragma unroll
                for (int tn = 0; tn < 8; tn++) {
                    mma_f16(acc[tm][tn], ah[tm], bf[tn][0], bf[tn][1]);
                    mma_f16(acc[tm][tn], al[tm], bf[tn][0], bf[tn][1]);
                }
        }
    }

    if (OUT16) {
        asm volatile("cp.async.wait_group 0;");
        __syncthreads();
        __half* st = (__half*)sm;
#pragma unroll
        for (int tm = 0; tm < 4; tm++) {
#pragma unroll
            for (int hf = 0; hf < 2; hf++) {
                int r = wm*64 + tm*16 + (lane >> 2) + hf*8;
                float bv = bias[r];
#pragma unroll
                for (int tn = 0; tn < 8; tn++) {
                    int col = wn*64 + tn*8 + (lane & 3)*2;
                    float x0 = acc[tm][tn][hf*2+0] + bv;
                    float x1 = acc[tm][tn][hf*2+1] + bv;
                    x0 = x0 > 0.f ? x0 : expf(x0) - 1.f;
                    x1 = x1 > 0.f ? x1 : expf(x1) - 1.f;
                    st[(size_t)col * TPITCH + r]       = __float2half(x0);
                    st[(size_t)(col+1) * TPITCH + r]   = __float2half(x1);
                }
            }
        }
        __syncthreads();
        __half* dst = out16 + ((size_t)bz * HWF + bn + tid) * CC;
        const uint4* srcv = (const uint4*)(st + (size_t)tid * TPITCH);
#pragma unroll
        for (int i = 0; i < 16; i++)
            ((uint4*)dst)[i] = srcv[i];
    } else {
        float* C = Cout + (size_t)bz * CC * HWF;
#pragma unroll
        for (int tm = 0; tm < 4; tm++) {
            int row = wm*64 + tm*16 + (lane >> 2);
#pragma unroll
            for (int hf = 0; hf < 2; hf++) {
                int r = row + hf*8;
                float bv = bias[r];
                float* dst = C + (size_t)r * HWF + bn + wn*64 + (lane & 3)*2;
#pragma unroll
                for (int tn = 0; tn < 8; tn++) {
                    float x0 = acc[tm][tn][hf*2+0] + bv;
                    float x1 = acc[tm][tn][hf*2+1] + bv;
                    x0 = x0 > 0.f ? x0 : expf(x0) - 1.f;
                    x1 = x1 > 0.f ? x1 : expf(x1) - 1.f;
                    *(float2*)(dst + tn*8) = make_float2(x0, x1);
                }
            }
        }
    }
}

// ===================== stencil + fuse1 fused (R8-verified) ===================
__device__ __forceinline__ float s0_at(const float* __restrict__ Gb, int b,
                                       int nyy, int nxx, int pyy, int pxx) {
    if ((unsigned)nyy >= 64u || (unsigned)pyy >= 64u) return 0.f;
    float s = 0.f;
#pragma unroll
    for (int dy = 0; dy < 3; dy++) {
        int gy = nyy + dy - 1, gpy = pyy + dy - 1;
        bool ok = (unsigned)gy < 64u && (unsigned)gpy < 64u;
#pragma unroll
        for (int dx = -1; dx <= 1; dx++) {
            int a = nxx + dx, c = pxx + dx;
            if (ok && (unsigned)a < 64u && (unsigned)c < 64u)
                s += Gb[((size_t)(gy*64 + a)) * NP + gpy*64 + c];
        }
    }
    return s * g_inv[b*NP + nyy*64 + nxx];
}

#define STENF1_SMEM (16642*4)

__global__ void __launch_bounds__(256) k_stenf1(const float* __restrict__ G,
                                                float* __restrict__ out) {
    extern __shared__ float dsm[];
    float* t3  = dsm;             // 3*64*64
    float* s0t = dsm + 12288;     // 64*64
    float* SA  = dsm + 16384;     // 64
    float* SB  = dsm + 16448;
    float* SC  = dsm + 16512;
    float* SD  = dsm + 16576;
    float* CN  = dsm + 16640;     // 2

    int bid = blockIdx.x;
    int b = bid >> 12;
    int rest = bid & 4095;
    int ny = rest >> 6, py = rest & 63;
    const float* Gb = G + (size_t)b * NP * NP;
    float* ob = out + (size_t)b * NP * NP;
    int tid = threadIdx.x;

#pragma unroll
    for (int dy = 0; dy < 3; dy++) {
        int gy = ny + dy - 1, gpy = py + dy - 1;
        bool ok = (unsigned)gy < 64 && (unsigned)gpy < 64;
        for (int idx = tid; idx < 4096; idx += 256) {
            int i = idx >> 6, jj = idx & 63;
            t3[dy*4096 + idx] = ok ? Gb[((size_t)(gy*64 + i)) * NP + gpy*64 + jj] : 0.f;
        }
    }

    {
        int g = tid >> 6;
        int e = tid & 63;
        float v;
        if (g == 0)      v = s0_at(Gb, b, ny-1, 63, py,   e);
        else if (g == 1) v = s0_at(Gb, b, ny,   e,  py-1, 63);
        else if (g == 2) v = s0_at(Gb, b, ny+1, 0,  py,   e);
        else             v = s0_at(Gb, b, ny,   e,  py+1, 0);
        (g == 0 ? SA : g == 1 ? SB : g == 2 ? SC : SD)[e] = v;
        if (tid == 0) CN[0] = s0_at(Gb, b, ny-1, 63, py-1, 63);
        if (tid == 1) CN[1] = s0_at(Gb, b, ny+1, 0,  py+1, 0);
    }
    __syncthreads();

    int px = tid & 63;
    int nx0 = tid >> 6;
    for (int nx = nx0; nx < 64; nx += 4) {
        float s = 0.f;
#pragma unroll
        for (int dy = 0; dy < 3; dy++)
#pragma unroll
            for (int dx = -1; dx <= 1; dx++) {
                int a = nx + dx, c = px + dx;
                if ((unsigned)a < 64 && (unsigned)c < 64)
                    s += t3[dy*4096 + a*64 + c];
            }
        s0t[nx*64 + px] = s * g_inv[b*NP + ny*64 + nx];
    }
    __syncthreads();

    for (int nx = nx0; nx < 64; nx += 4) {
        float f = s0t[nx*64 + px];
        float tm, tp;
        if (nx > 0) tm = (px > 0) ? s0t[(nx-1)*64 + px-1] : SB[nx-1];
        else        tm = (px > 0) ? SA[px-1] : CN[0];
        if (nx < 63) tp = (px < 63) ? s0t[(nx+1)*64 + px+1] : SD[nx+1];
        else         tp = (px < 63) ? SC[px+1] : CN[1];
        ob[((size_t)(ny*64 + nx)) * NP + py*64 + px] = f + tm + tp;
    }
}

// ===================== fused fuse2(permuted) + softmax stats ================
// F = fused1 in ORIGINAL layout. Permuted coords: rp=swap(r), cp=swap(c),
// swap(x) = (x&63)*64 + (x>>6). l(rp,cp) = [F[r][c] + F[o(rp-1)][o(cp-1)]
// + F[o(rp+1)][o(cp+1)]] * eq[rp] * SCALE, flat guards on rp±1 / cp±1.
__global__ void __launch_bounds__(256) k_stats(const float* __restrict__ F) {
    int tid = threadIdx.x;
    int chunk = blockIdx.x;         // 0..CHUNKS-1 (orig-row chunks of 64)
    int half = blockIdx.y;          // 0/1 column halves
    int b = blockIdx.z;
    const float* Fb = F + (size_t)b * NP * NP;
    int r0 = chunk * 64;
    int cbase = half * 2048 + tid;

    int cmc[8], cpc[8];
    float mx[8], sm[8];
#pragma unroll
    for (int k = 0; k < 8; k++) {
        int c = cbase + k * 256;
        int cy = c >> 6, cxl = c & 63;
        int cp = cxl * 64 + cy;
        cmc[k] = (cp > 0)    ? ((cy > 0)  ? c - 64 : 4032 + cxl - 1) : -1;
        cpc[k] = (cp < 4095) ? ((cy < 63) ? c + 64 : cxl + 1)        : -1;
        mx[k] = -1e30f; sm[k] = 0.f;
    }

    for (int r = r0; r < r0 + 64; r++) {
        int ny = r >> 6, nx = r & 63;
        int rp = nx * 64 + ny;
        float eqs = g_eq[rp] * SCALEF;
        int rm  = (rp > 0)    ? ((ny > 0)  ? r - 64 : 4032 + nx - 1) : -1;
        int rpl = (rp < 4095) ? ((ny < 63) ? r + 64 : nx + 1)        : -1;
        const float* row0 = Fb + (size_t)r * NP;
        const float* rowm = Fb + (size_t)(rm  < 0 ? 0 : rm ) * NP;
        const float* rowp = Fb + (size_t)(rpl < 0 ? 0 : rpl) * NP;
#pragma unroll
        for (int k = 0; k < 8; k++) {
            int c = cbase + k * 256;
            float v = row0[c];
            if (rm  >= 0 && cmc[k] >= 0) v += rowm[cmc[k]];
            if (rpl >= 0 && cpc[k] >= 0) v += rowp[cpc[k]];
            float l = v * eqs;
            if (l > mx[k]) { sm[k] = sm[k] * expf(mx[k] - l) + 1.f; mx[k] = l; }
            else           sm[k] += expf(l - mx[k]);
        }
    }
#pragma unroll
    for (int k = 0; k < 8; k++) {
        int c = cbase + k * 256;
        int cp = (c & 63) * 64 + (c >> 6);
        g_pmax[((size_t)(b * CHUNKS + chunk)) * NP + cp] = mx[k];
        g_psum[((size_t)(b * CHUNKS + chunk)) * NP + cp] = sm[k];
    }
}

__global__ void k_smax2() {
    int idx = blockIdx.x * blockDim.x + threadIdx.x;
    if (idx >= BT * NP) return;
    int b = idx / NP, col = idx % NP;
    float M = -1e30f;
    for (int i = 0; i < CHUNKS; i++)
        M = fmaxf(M, g_pmax[((size_t)(b * CHUNKS + i)) * NP + col]);
    float S = 0.f;
    for (int i = 0; i < CHUNKS; i++)
        S += g_psum[((size_t)(b * CHUNKS + i)) * NP + col] *
             expf(g_pmax[((size_t)(b * CHUNKS + i)) * NP + col] - M);
    g_cmax[idx] = M;
    g_csum[idx] = S;
    g_lthr[idx] = M + logf(SEL_THR * S);
}

// ===================== sparse selection (chunk-skip) ========================
__global__ void k_sel2(const float* __restrict__ F) {
    int c = blockIdx.x * 256 + threadIdx.x;   // orig col
    int chunk = blockIdx.y;
    int b = blockIdx.z;
    int cy = c >> 6, cxl = c & 63;
    int cp = cxl * 64 + cy;
    int lb = b * NP + cp;
    int ccidx = lb * CHUNKS + chunk;
    float lth = g_lthr[lb];
    if (g_pmax[((size_t)(b * CHUNKS + chunk)) * NP + cp] <= lth) {
        g_ccnt[ccidx] = 0;
        return;
    }
    float M = g_cmax[lb];
    float Sin = 1.f / g_csum[lb];
    int cmcv = (cp > 0)    ? ((cy > 0)  ? c - 64 : 4032 + cxl - 1) : -1;
    int cpcv = (cp < 4095) ? ((cy < 63) ? c + 64 : cxl + 1)        : -1;
    const float* Fb = F + (size_t)b * NP * NP;
    int s = 0;
    size_t slotbase = ((size_t)lb * CHUNKS + chunk) * SLOTS;
    for (int r = chunk * 64; r < chunk * 64 + 64; r++) {
        int ny = r >> 6, nx = r & 63;
        int rp = nx * 64 + ny;
        float eqv = g_eq[rp];
        float eqs = eqv * SCALEF;
        int rm  = (rp > 0)    ? ((ny > 0)  ? r - 64 : 4032 + nx - 1) : -1;
        int rpl = (rp < 4095) ? ((ny < 63) ? r + 64 : nx + 1)        : -1;
        float v = Fb[(size_t)r * NP + c];
        if (rm  >= 0 && cmcv >= 0) v += Fb[(size_t)rm  * NP + cmcv];
        if (rpl >= 0 && cpcv >= 0) v += Fb[(size_t)rpl * NP + cpcv];
        float l = v * eqs;
        if (l > lth && eqv != 0.f && s < SLOTS) {
            g_cidx[slotbase + s] = rp;
            g_cwgt[slotbase + s] = expf(l - M) * Sin * eqv;
            s++;
        }
    }
    g_ccnt[ccidx] = s;
}

__global__ void k_merge() {
    int idx = blockIdx.x * blockDim.x + threadIdx.x;
    if (idx >= BT * NP) return;
    int cnt = 0;
    size_t ob = (size_t)idx * KMAX;
    for (int ch = 0; ch < CHUNKS; ch++) {
        int c = g_ccnt[idx * CHUNKS + ch];
        size_t sb = ((size_t)idx * CHUNKS + ch) * SLOTS;
        for (int i = 0; i < c && cnt < KMAX; i++) {
            g_midx[ob + cnt] = g_cidx[sb + i];
            g_mwgt[ob + cnt] = g_cwgt[sb + i];
            cnt++;
        }
    }
    g_mcnt[idx] = cnt;
}

// ===================== sparse apply + transposed-conv gather ================
__global__ void k_apply() {
    int wid = threadIdx.x >> 5, lane = threadIdx.x & 31;
    int P = blockIdx.x * 8 + wid;
    int b = blockIdx.y;
    int Y = P >> 7, X = P & 127;
    const __half* bgc = g_bgcl + (size_t)b * HWF * CC;
    float4 acc = make_float4(0.f, 0.f, 0.f, 0.f);
#pragma unroll
    for (int di = 0; di < 4; di++) {
        int ty = Y + 1 - di;
        if (ty < 0 || (ty & 1)) continue;
        int my = ty >> 1;
        if (my >= HS) continue;
#pragma unroll
        for (int dj = 0; dj < 4; dj++) {
            int tx = X + 1 - dj;
            if (tx < 0 || (tx & 1)) continue;
            int mx = tx >> 1;
            if (mx >= HS) continue;
            int p = my * 64 + mx;
            int lb = b * NP + p;
            int cnt = g_mcnt[lb];
            const int*   il = g_midx + (size_t)lb * KMAX;
            const float* wl = g_mwgt + (size_t)lb * KMAX;
            for (int i = 0; i < cnt; i++) {
                int m = il[i];
                float w = wl[i];
                int miy = m >> 6, mix = m & 63;
                int Ys = 2*miy + di - 1, Xs = 2*mix + dj - 1;
                if ((unsigned)Ys >= HH || (unsigned)Xs >= WW) continue;
                union { uint2 u; __half2 h[2]; } v;
                v.u = *(const uint2*)(bgc + ((size_t)(Ys * WW + Xs)) * CC + lane * 4);
                float2 a0 = __half22float2(v.h[0]);
                float2 a1 = __half22float2(v.h[1]);
                acc.x += w * a0.x; acc.y += w * a0.y;
                acc.z += w * a1.x; acc.w += w * a1.y;
            }
        }
    }
    union { __half2 h[2]; uint2 u; } cv;
    cv.h[0] = __floats2half2_rn(acc.x * 0.25f, acc.y * 0.25f);
    cv.h[1] = __floats2half2_rn(acc.z * 0.25f, acc.w * 0.25f);
    *(uint2*)(g_y16 + ((size_t)b * HWF + P) * CC + lane * 4) = cv.u;
}

// ===================== host orchestration =====================
extern "C" void kernel_launch(void* const* d_in, const int* in_sizes, int n_in,
                              void* d_out, int out_size) {
    const float* fg   = (const float*)d_in[0];
    const float* bg   = (const float*)d_in[1];
    const float* mask = (const float*)d_in[2];
    const float* w1   = (const float*)d_in[3];
    const float* b1   = (const float*)d_in[4];
    const float* w2   = (const float*)d_in[5];
    const float* b2   = (const float*)d_in[6];
    float* out = (float*)d_out;

    cudaFuncSetAttribute(mgemm, cudaFuncAttributeMaxDynamicSharedMemorySize, MGEMM_SMEM);
    cudaFuncSetAttribute(cgemm<0>, cudaFuncAttributeMaxDynamicSharedMemorySize, CGEMM_SMEM);
    cudaFuncSetAttribute(cgemm<1>, cudaFuncAttributeMaxDynamicSharedMemorySize, CGEMM_SMEM);
    cudaFuncSetAttribute(k_stenf1, cudaFuncAttributeMaxDynamicSharedMemorySize, STENF1_SMEM);

    __nv_bfloat16 *bh, *bl, *fh, *fl;
    __half *y16, *h16, *w1h, *w1l, *w2h, *w2l;
    float *bufA, *bufB;
    cudaGetSymbolAddress((void**)&bh, g_bh);     cudaGetSymbolAddress((void**)&bl, g_bl);
    cudaGetSymbolAddress((void**)&fh, g_fh);     cudaGetSymbolAddress((void**)&fl, g_fl);
    cudaGetSymbolAddress((void**)&y16, g_y16);   cudaGetSymbolAddress((void**)&h16, g_h16);
    cudaGetSymbolAddress((void**)&w1h, g_w1h16); cudaGetSymbolAddress((void**)&w1l, g_w1l16);
    cudaGetSymbolAddress((void**)&w2h, g_w2h16); cudaGetSymbolAddress((void**)&w2l, g_w2l16);
    cudaGetSymbolAddress((void**)&bufA, g_bufA);
    cudaGetSymbolAddress((void**)&bufB, g_bufB);

    // prep
    k_half    <<<(BT*NP*CC + 255)/256, 256>>>(bg, bh, bl);
    k_half    <<<(BT*NP*CC + 255)/256, 256>>>(fg, fh, fl);
    k_ss      <<<(BT*NP + 255)/256, 256>>>();
    k_inv     <<<(BT*NP + 255)/256, 256>>>();
    k_bgcl    <<<dim3(HWF/32, CC/32, BT), 256>>>(bg);
    k_eq      <<<16, 256>>>(mask);
    k_wreorder<<<(CC*K1 + 255)/256, 256>>>(w1, w1h, w1l);
    k_wreorder<<<(CC*K1 + 255)/256, 256>>>(w2, w2h, w2l);

    // GEMM1: G[u][v] = sum_c b[u][c] f[v][c]  (bf16 3-term) -> bufA
    mgemm<<<dim3(32, 32, BT), 256, MGEMM_SMEM>>>(
        bh, bl, fh, fl, bufA, CC, NP,
        (size_t)NP * CC, (size_t)NP * CC, (size_t)NP * NP);

    // stencil + fuse1 -> F (bufB, original layout)
    k_stenf1<<<BT * 4096, 256, STENF1_SMEM>>>(bufA, bufB);

    // fused permuted-fuse2 + softmax stats
    k_stats<<<dim3(CHUNKS, 2, BT), 256>>>(bufB);
    k_smax2<<<32, 256>>>();

    // sparse selection (chunk-skip) + merge
    k_sel2 <<<dim3(16, CHUNKS, BT), 256>>>(bufB);
    k_merge<<<32, 256>>>();

    // sparse attention apply + transposed-conv gather -> y16
    k_apply<<<dim3(HWF/8, BT), 256>>>();

    // conv1 + ELU (implicit, fp16 2-term W) -> h16 image
    cgemm<1><<<dim3(HWF/256, 1, BT), 256, CGEMM_SMEM>>>(
        w1h, w1l, y16, nullptr, h16, b1);

    // conv2 + ELU (implicit) -> out fp32 NCHW
    cgemm<0><<<dim3(HWF/256, 1, BT), 256, CGEMM_SMEM>>>(
        w2h, w2l, h16, out, nullptr, b2);
}

// round 12
// speedup vs baseline: 1.1147x; 1.1147x over previous
#include <cuda_runtime.h>
#include <cuda_bf16.h>
#include <cuda_fp16.h>
#include <math.h>
#include <stdint.h>

#define BT 2
#define CC 128
#define HH 128
#define WW 128
#define HS 64
#define NP 4096
#define K1 1152
#define HWF 16384
#define SCALEF 10.0f
#define SEL_THR 1e-7f
#define SLOTS 16
#define KMAX 128

// ===================== scratch =====================
__device__ __align__(256) __nv_bfloat16 g_bh [(size_t)BT*NP*CC];
__device__ __align__(256) __nv_bfloat16 g_bl [(size_t)BT*NP*CC];
__device__ __align__(256) __nv_bfloat16 g_fh [(size_t)BT*NP*CC];
__device__ __align__(256) __nv_bfloat16 g_fl [(size_t)BT*NP*CC];
__device__ __align__(256) __half        g_bgcl[(size_t)BT*HWF*CC]; // bg channels-last fp16
__device__ __align__(256) __half        g_y16 [(size_t)BT*HWF*CC]; // y image channels-last
__device__ __align__(256) __half        g_h16 [(size_t)BT*HWF*CC]; // h image channels-last
__device__ __align__(256) __half        g_w1h16[CC*K1], g_w1l16[CC*K1];
__device__ __align__(256) __half        g_w2h16[CC*K1], g_w2l16[CC*K1];
__device__ __align__(256) float g_bufA[(size_t)BT*NP*NP];
__device__ __align__(256) float g_bufB[(size_t)BT*NP*NP];
__device__ int   g_cidx[(size_t)BT*NP*32*SLOTS];
__device__ float g_cwgt[(size_t)BT*NP*32*SLOTS];
__device__ int   g_ccnt[BT*NP*32];
__device__ int   g_midx[(size_t)BT*NP*KMAX];
__device__ float g_mwgt[(size_t)BT*NP*KMAX];
__device__ int   g_mcnt[BT*NP];
__device__ float g_eq  [NP];
__device__ float g_ss  [BT*NP];
__device__ float g_inv [BT*NP];
__device__ float g_pmax[BT*32*NP];
__device__ float g_psum[BT*32*NP];
__device__ float g_cmax[BT*NP];
__device__ float g_csum[BT*NP];
__device__ float g_lthr[BT*NP];

__device__ __forceinline__ void split_store(__nv_bfloat16* H, __nv_bfloat16* L,
                                            size_t idx, float v) {
    __nv_bfloat16 h = __float2bfloat16(v);
    H[idx] = h;
    L[idx] = __float2bfloat16(v - __bfloat162float(h));
}
__device__ __forceinline__ void split_store16(__half* H, __half* L, size_t idx, float v) {
    __half h = __float2half(v);
    H[idx] = h;
    L[idx] = __float2half(v - __half2float(h));
}
__device__ __forceinline__ uint32_t smem_u32(const void* p) {
    uint32_t a;
    asm("{ .reg .u64 t; cvta.to.shared.u64 t, %1; cvt.u32.u64 %0, t; }" : "=r"(a) : "l"(p));
    return a;
}
__device__ __forceinline__ void ldsm_x4(uint32_t (&r)[4], uint32_t addr) {
    asm volatile("ldmatrix.sync.aligned.m8n8.x4.shared.b16 {%0,%1,%2,%3}, [%4];"
                 : "=r"(r[0]), "=r"(r[1]), "=r"(r[2]), "=r"(r[3]) : "r"(addr));
}
__device__ __forceinline__ void mma_bf16(float (&d)[4], const uint32_t (&a)[4],
                                         uint32_t b0, uint32_t b1) {
    asm volatile("mma.sync.aligned.m16n8k16.row.col.f32.bf16.bf16.f32 "
        "{%0,%1,%2,%3}, {%4,%5,%6,%7}, {%8,%9}, {%0,%1,%2,%3};"
        : "+f"(d[0]), "+f"(d[1]), "+f"(d[2]), "+f"(d[3])
        : "r"(a[0]), "r"(a[1]), "r"(a[2]), "r"(a[3]), "r"(b0), "r"(b1));
}
__device__ __forceinline__ void mma_f16(float (&d)[4], const uint32_t (&a)[4],
                                        uint32_t b0, uint32_t b1) {
    asm volatile("mma.sync.aligned.m16n8k16.row.col.f32.f16.f16.f32 "
        "{%0,%1,%2,%3}, {%4,%5,%6,%7}, {%8,%9}, {%0,%1,%2,%3};"
        : "+f"(d[0]), "+f"(d[1]), "+f"(d[2]), "+f"(d[3])
        : "r"(a[0]), "r"(a[1]), "r"(a[2]), "r"(a[3]), "r"(b0), "r"(b1));
}
__device__ __forceinline__ void cpasync16(uint32_t saddr, const void* g) {
    asm volatile("cp.async.cg.shared.global [%0], [%1], 16;" :: "r"(saddr), "l"(g));
}
__device__ __forceinline__ void cpasync16z(uint32_t saddr, const void* g, int szbytes) {
    asm volatile("cp.async.cg.shared.global [%0], [%1], 16, %2;"
                 :: "r"(saddr), "l"(g), "r"(szbytes));
}

// ===================== prep =====================
__global__ void k_half(const float* __restrict__ src, __nv_bfloat16* H, __nv_bfloat16* L) {
    int idx = blockIdx.x * blockDim.x + threadIdx.x;
    if (idx >= BT * NP * CC) return;
    int c = idx & 127;
    int t = idx >> 7;
    int n = t & 4095;
    int b = t >> 12;
    int y = n >> 6, x = n & 63;
    float v = src[(((size_t)b*CC + c)*HH + 2*y)*WW + 2*x];
    split_store(H, L, (size_t)idx, v);
}

__global__ void k_ss() {
    int idx = blockIdx.x * blockDim.x + threadIdx.x;
    if (idx >= BT * NP) return;
    const __nv_bfloat162* h2 = (const __nv_bfloat162*)(g_bh + (size_t)idx * CC);
    const __nv_bfloat162* l2 = (const __nv_bfloat162*)(g_bl + (size_t)idx * CC);
    float s = 0.f;
#pragma unroll
    for (int c = 0; c < CC/2; c++) {
        float2 a = __bfloat1622float2(h2[c]);
        float2 bb = __bfloat1622float2(l2[c]);
        float v0 = a.x + bb.x, v1 = a.y + bb.y;
        s += v0*v0 + v1*v1;
    }
    g_ss[idx] = s;
}

__global__ void k_inv() {
    int idx = blockIdx.x * blockDim.x + threadIdx.x;
    if (idx >= BT * NP) return;
    int b = idx >> 12, n = idx & 4095;
    int ny = n >> 6, nx = n & 63;
    float s = 0.f;
#pragma unroll
    for (int i = 0; i < 3; i++)
#pragma unroll
        for (int j = 0; j < 3; j++) {
            int y = ny + i - 1, x = nx + j - 1;
            if ((unsigned)y < 64u && (unsigned)x < 64u)
                s += g_ss[b*NP + y*64 + x];
        }
    g_inv[idx] = 1.f / fmaxf(sqrtf(s), 1e-4f);
}

__global__ void k_bgcl(const float* __restrict__ bg) {
    __shared__ float tile[32][33];
    int b = blockIdx.z;
    int c0 = blockIdx.y * 32;
    int p0 = blockIdx.x * 32;
    int tx = threadIdx.x & 31, ty = threadIdx.x >> 5;
#pragma unroll
    for (int k = 0; k < 4; k++) {
        int c = c0 + ty + k*8;
        tile[ty + k*8][tx] = bg[((size_t)(b*CC + c))*HWF + p0 + tx];
    }
    __syncthreads();
#pragma unroll
    for (int k = 0; k < 4; k++) {
        int p = p0 + ty + k*8;
        g_bgcl[((size_t)(b*HWF + p))*CC + c0 + tx] = __float2half(tile[tx][ty + k*8]);
    }
}

__global__ void k_eq(const float* __restrict__ mask) {
    int n = blockIdx.x * blockDim.x + threadIdx.x;
    if (n >= NP) return;
    int ny = n / HS, nx = n % HS;
    float s = 0.f;
#pragma unroll
    for (int i = 0; i < 3; i++)
#pragma unroll
        for (int j = 0; j < 3; j++) {
            int y = ny + i - 1, x = nx + j - 1;
            if ((unsigned)y < HS && (unsigned)x < HS)
                s += mask[(2*y)*WW + 2*x];
        }
    g_eq[n] = ((s / 9.f) == 0.f) ? 1.f : 0.f;
}

__global__ void k_wreorder(const float* __restrict__ w, __half* H, __half* L) {
    int idx = blockIdx.x * blockDim.x + threadIdx.x;
    if (idx >= CC * K1) return;
    int r = idx / K1;
    int rem = idx % K1;
    int tap = rem >> 7;
    int c = rem & 127;
    split_store16(H, L, (size_t)idx, w[r * K1 + c * 9 + tap]);
}

// ===================== bf16-split GEMM (3-term, 128x128) — GEMM1 =============
#define KT 32
#define STAGES 3
#define STAGE_BYTES (4*128*KT*2)
#define MGEMM_SMEM (STAGES*STAGE_BYTES)

__global__ void __launch_bounds__(256, 1) mgemm(
    const __nv_bfloat16* __restrict__ Ah, const __nv_bfloat16* __restrict__ Al,
    const __nv_bfloat16* __restrict__ Bh, const __nv_bfloat16* __restrict__ Bl,
    float* __restrict__ C, int K, int N,
    size_t sA, size_t sB, size_t sC)
{
    extern __shared__ char sm[];
    const uint32_t smb = smem_u32(sm);
    const int tid = threadIdx.x;
    const int bz = blockIdx.z;
    const int bm = blockIdx.y * 128;
    const int bn = blockIdx.x * 128;
    C += sC * bz;

    const int j   = tid >> 6;
    const int l64 = tid & 63;
    const int rbase = (j < 2) ? bm : bn;
    const __nv_bfloat16* src =
        (j == 0) ? Ah + sA*bz : (j == 1) ? Al + sA*bz : (j == 2) ? Bh + sB*bz : Bl + sB*bz;

    const int NC = K >> 5;

#pragma unroll
    for (int s = 0; s < STAGES - 1; s++) {
        const int kc = s * KT;
#pragma unroll
        for (int i = 0; i < 8; i++) {
            int id = l64 + i * 64;
            int row = id >> 2, ch = id & 3;
            const void* g = src + (size_t)(rbase + row) * K + kc + ch * 8;
            uint32_t sa = smb + s*STAGE_BYTES + j*8192 + row*64 + ((ch ^ ((row >> 1) & 3)) << 4);
            cpasync16(sa, g);
        }
        asm volatile("cp.async.commit_group;");
    }

    const int wid = tid >> 5, lane = tid & 31;
    const int wm = wid & 1, wn = wid >> 1;

    float acc[4][4][4];
#pragma unroll
    for (int a = 0; a < 4; a++)
#pragma unroll
        for (int bb = 0; bb < 4; bb++)
#pragma unroll
            for (int c = 0; c < 4; c++) acc[a][bb][c] = 0.f;

    for (int i = 0; i < NC; i++) {
        asm volatile("cp.async.wait_group 1;");
        __syncthreads();

        if (i + STAGES - 1 < NC) {
            const int s2 = (i + STAGES - 1) % STAGES;
            const int kc = (i + STAGES - 1) * KT;
#pragma unroll
            for (int it = 0; it < 8; it++) {
                int id = l64 + it * 64;
                int row = id >> 2, ch = id & 3;
                const void* g = src + (size_t)(rbase + row) * K + kc + ch * 8;
                uint32_t sa = smb + s2*STAGE_BYTES + j*8192 + row*64 + ((ch ^ ((row >> 1) & 3)) << 4);
                cpasync16(sa, g);
            }
        }
        asm volatile("cp.async.commit_group;");

        const uint32_t stb = smb + (i % STAGES) * STAGE_BYTES;
#pragma unroll
        for (int h = 0; h < 2; h++) {
            uint32_t ah[4][4], al[4][4];
            uint32_t bh[4][2], bl[4][2];
#pragma unroll
            for (int tm = 0; tm < 4; tm++) {
                int row = wm*64 + tm*16 + (lane & 15);
                int ch  = 2*h + (lane >> 4);
                uint32_t ad = stb + row*64 + ((ch ^ ((row >> 1) & 3)) << 4);
                ldsm_x4(ah[tm], ad);
                ldsm_x4(al[tm], ad + 8192);
            }
#pragma unroll
            for (int tp = 0; tp < 2; tp++) {
                int row = wn*32 + tp*16 + ((lane >> 4) << 3) + (lane & 7);
                int ch  = 2*h + ((lane >> 3) & 1);
                uint32_t bd = stb + 16384 + row*64 + ((ch ^ ((row >> 1) & 3)) << 4);
                uint32_t r[4];
                ldsm_x4(r, bd);
                bh[tp*2][0] = r[0]; bh[tp*2][1] = r[1];
                bh[tp*2+1][0] = r[2]; bh[tp*2+1][1] = r[3];
                ldsm_x4(r, bd + 8192);
                bl[tp*2][0] = r[0]; bl[tp*2][1] = r[1];
                bl[tp*2+1][0] = r[2]; bl[tp*2+1][1] = r[3];
            }
#pragma unroll
            for (int tm = 0; tm < 4; tm++)
#pragma unroll
                for (int tn = 0; tn < 4; tn++) {
                    mma_bf16(acc[tm][tn], ah[tm], bh[tn][0], bh[tn][1]);
                    mma_bf16(acc[tm][tn], ah[tm], bl[tn][0], bl[tn][1]);
                    mma_bf16(acc[tm][tn], al[tm], bh[tn][0], bh[tn][1]);
                }
        }
    }

#pragma unroll
    for (int tm = 0; tm < 4; tm++) {
        int row = bm + wm*64 + tm*16 + (lane >> 2);
#pragma unroll
        for (int hf = 0; hf < 2; hf++) {
            int r = row + hf*8;
            float* dst = C + (size_t)r * N + bn + wn*32 + (lane & 3)*2;
#pragma unroll
            for (int tn = 0; tn < 4; tn++)
                *(float2*)(dst + tn*8) = make_float2(acc[tm][tn][hf*2+0], acc[tm][tn][hf*2+1]);
        }
    }
}

// ===================== implicit conv GEMM: 128ch x 256pix, fp16 2-term W =====
#define CSTAGE 32768
#define CGEMM_SMEM (STAGES*CSTAGE)
#define TPITCH 136

template<int OUT16>
__global__ void __launch_bounds__(256, 1) cgemm(
    const __half* __restrict__ Wh, const __half* __restrict__ Wl,
    const __half* __restrict__ img,
    float* __restrict__ Cout, __half* __restrict__ out16,
    const float* __restrict__ bias)
{
    extern __shared__ char sm[];
    const uint32_t smb = smem_u32(sm);
    const int tid = threadIdx.x;
    const int bz = blockIdx.z;
    const int bn = blockIdx.x * 256;
    const __half* ib = img + (size_t)bz * HWF * CC;

    const int NC = K1 >> 5;   // 36

    auto load_stage = [&](int s, int kc) {
#pragma unroll
        for (int it = 0; it < 2; it++) {
            int id = tid + it * 256;
            int row = id >> 2, ch = id & 3;
            uint32_t swz = (uint32_t)(row * 64 + ((ch ^ ((row >> 1) & 3)) << 4));
            cpasync16(smb + s*CSTAGE + swz,        Wh + (size_t)row * K1 + kc + ch * 8);
            cpasync16(smb + s*CSTAGE + 8192 + swz, Wl + (size_t)row * K1 + kc + ch * 8);
        }
        int tap = kc >> 7;
        int ki = tap / 3, kj = tap - ki * 3;
        int c0 = kc & 127;
#pragma unroll
        for (int it = 0; it < 4; it++) {
            int id = tid + it * 256;
            int row = id >> 2, ch = id & 3;
            int p = bn + row;
            int Y = (p >> 7) + ki - 1, X = (p & 127) + kj - 1;
            bool ok = (unsigned)Y < HH && (unsigned)X < WW;
            const __half* g = ok ? ib + ((size_t)(Y * WW + X)) * CC + c0 + ch * 8 : ib;
            uint32_t swz = (uint32_t)(row * 64 + ((ch ^ ((row >> 1) & 3)) << 4));
            cpasync16z(smb + s*CSTAGE + 16384 + swz, g, ok ? 16 : 0);
        }
        asm volatile("cp.async.commit_group;");
    };

#pragma unroll
    for (int s = 0; s < STAGES - 1; s++) load_stage(s, s * KT);

    const int wid = tid >> 5, lane = tid & 31;
    const int wm = wid & 1, wn = wid >> 1;

    float acc[4][8][4];
#pragma unroll
    for (int a = 0; a < 4; a++)
#pragma unroll
        for (int bb = 0; bb < 8; bb++)
#pragma unroll
            for (int c = 0; c < 4; c++) acc[a][bb][c] = 0.f;

    for (int i = 0; i < NC; i++) {
        asm volatile("cp.async.wait_group 1;");
        __syncthreads();

        if (i + STAGES - 1 < NC)
            load_stage((i + STAGES - 1) % STAGES, (i + STAGES - 1) * KT);
        else
            asm volatile("cp.async.commit_group;");

        const uint32_t stb = smb + (i % STAGES) * CSTAGE;
#pragma unroll
        for (int h = 0; h < 2; h++) {
            uint32_t ah[4][4], al[4][4];
            uint32_t bf[8][2];
#pragma unroll
            for (int tm = 0; tm < 4; tm++) {
                int row = wm*64 + tm*16 + (lane & 15);
                int ch  = 2*h + (lane >> 4);
                uint32_t ad = stb + row*64 + ((ch ^ ((row >> 1) & 3)) << 4);
                ldsm_x4(ah[tm], ad);
                ldsm_x4(al[tm], ad + 8192);
            }
#pragma unroll
            for (int tb = 0; tb < 4; tb++) {
                int row = wn*64 + tb*16 + ((lane >> 4) << 3) + (lane & 7);
                int ch  = 2*h + ((lane >> 3) & 1);
                uint32_t bd = stb + 16384 + row*64 + ((ch ^ ((row >> 1) & 3)) << 4);
                uint32_t r[4];
                ldsm_x4(r, bd);
                bf[tb*2][0] = r[0]; bf[tb*2][1] = r[1];
                bf[tb*2+1][0] = r[2]; bf[tb*2+1][1] = r[3];
            }
#pragma unroll
            for (int tm = 0; tm < 4; tm++)
#pragma unroll
                for (int tn = 0; tn < 8; tn++) {
                    mma_f16(acc[tm][tn], ah[tm], bf[tn][0], bf[tn][1]);
                    mma_f16(acc[tm][tn], al[tm], bf[tn][0], bf[tn][1]);
                }
        }
    }

    if (OUT16) {
        asm volatile("cp.async.wait_group 0;");
        __syncthreads();
        __half* st = (__half*)sm;
#pragma unroll
        for (int tm = 0; tm < 4; tm++) {
#pragma unroll
            for (int hf = 0; hf < 2; hf++) {
                int r = wm*64 + tm*16 + (lane >> 2) + hf*8;
                float bv = bias[r];
#pragma unroll
                for (int tn = 0; tn < 8; tn++) {
                    int col = wn*64 + tn*8 + (lane & 3)*2;
                    float x0 = acc[tm][tn][hf*2+0] + bv;
                    float x1 = acc[tm][tn][hf*2+1] + bv;
                    x0 = x0 > 0.f ? x0 : expf(x0) - 1.f;
                    x1 = x1 > 0.f ? x1 : expf(x1) - 1.f;
                    st[(size_t)col * TPITCH + r]       = __float2half(x0);
                    st[(size_t)(col+1) * TPITCH + r]   = __float2half(x1);
                }
            }
        }
        __syncthreads();
        __half* dst = out16 + ((size_t)bz * HWF + bn + tid) * CC;
        const uint4* srcv = (const uint4*)(st + (size_t)tid * TPITCH);
#pragma unroll
        for (int i = 0; i < 16; i++)
            ((uint4*)dst)[i] = srcv[i];
    } else {
        float* C = Cout + (size_t)bz * CC * HWF;
#pragma unroll
        for (int tm = 0; tm < 4; tm++) {
            int row = wm*64 + tm*16 + (lane >> 2);
#pragma unroll
            for (int hf = 0; hf < 2; hf++) {
                int r = row + hf*8;
                float bv = bias[r];
                float* dst = C + (size_t)r * HWF + bn + wn*64 + (lane & 3)*2;
#pragma unroll
                for (int tn = 0; tn < 8; tn++) {
                    float x0 = acc[tm][tn][hf*2+0] + bv;
                    float x1 = acc[tm][tn][hf*2+1] + bv;
                    x0 = x0 > 0.f ? x0 : expf(x0) - 1.f;
                    x1 = x1 > 0.f ? x1 : expf(x1) - 1.f;
                    *(float2*)(dst + tn*8) = make_float2(x0, x1);
                }
            }
        }
    }
}

// ===================== stencil =====================
__global__ void __launch_bounds__(256) k_stencil9(const float* __restrict__ G,
                                                  float* __restrict__ out) {
    __shared__ float t3[3][64][64];
    int bid = blockIdx.x;
    int b = bid >> 12;
    int rest = bid & 4095;
    int ny = rest >> 6, py = rest & 63;
    const float* Gb = G + (size_t)b * NP * NP;
    float* ob = out + (size_t)b * NP * NP;
    int tid = threadIdx.x;

#pragma unroll
    for (int dy = 0; dy < 3; dy++) {
        int gy = ny + dy - 1, gpy = py + dy - 1;
        bool ok = (unsigned)gy < 64 && (unsigned)gpy < 64;
        for (int idx = tid; idx < 4096; idx += 256) {
            int i = idx >> 6, jj = idx & 63;
            t3[dy][i][jj] = ok ? Gb[((size_t)(gy*64 + i)) * NP + gpy*64 + jj] : 0.f;
        }
    }
    __syncthreads();

    int px = tid & 63;
    int nx0 = tid >> 6;
    for (int nx = nx0; nx < 64; nx += 4) {
        float s = 0.f;
#pragma unroll
        for (int dy = 0; dy < 3; dy++)
#pragma unroll
            for (int dx = -1; dx <= 1; dx++) {
                int a = nx + dx, c = px + dx;
                if ((unsigned)a < 64 && (unsigned)c < 64)
                    s += t3[dy][a][c];
            }
        ob[((size_t)(ny*64 + nx)) * NP + py*64 + px] = s * g_inv[b*NP + ny*64 + nx];
    }
}

// ===================== fuse1 + permutation =====================
__global__ void k_fuseperm(const float* __restrict__ in, float* __restrict__ out) {
    __shared__ float tile[64 * 65];
    int brow = blockIdx.x;
    int b = brow / NP, rp = brow % NP;
    int nx = rp >> 6, ny = rp & 63;
    int r = ny * 64 + nx;
    const float* src = in + (size_t)b * NP * NP;
    float*       dst = out + ((size_t)b * NP + rp) * NP;
    int tid = threadIdx.x;
    for (int k = tid; k < NP; k += 256) {
        float f = src[(size_t)r * NP + k];
        if (r > 0 && k > 0)           f += src[(size_t)(r-1) * NP + k - 1];
        if (r < NP-1 && k < NP-1)     f += src[(size_t)(r+1) * NP + k + 1];
        tile[(k & 63) * 65 + (k >> 6)] = f;
    }
    __syncthreads();
    for (int j = tid; j < NP; j += 256)
        dst[j] = tile[(j >> 6) * 65 + (j & 63)];
}

// ===================== softmax stats (fuse2 on the fly) =====================
__global__ void k_smax1(const float* __restrict__ in) {
    int col = blockIdx.x * 256 + threadIdx.x;
    int chunk = blockIdx.y;
    int b = blockIdx.z;
    int lane = threadIdx.x & 31;
    const float* base = in + (size_t)b * NP * NP;
    int r0 = chunk * 128;

    float pm1 = (r0 > 0) ? base[(size_t)(r0-1) * NP + col] : 0.f;
    float p0  = base[(size_t)r0 * NP + col];
    float pp1 = (r0 + 1 < NP) ? base[(size_t)(r0+1) * NP + col] : 0.f;

    float mx = -1e30f, sm = 0.f;
    for (int r = r0; r < r0 + 128; r++) {
        float um1 = __shfl_up_sync(0xffffffffu, pm1, 1);
        if (lane == 0)
            um1 = (r > 0 && col > 0) ? base[(size_t)(r-1) * NP + col - 1] : 0.f;
        float dp1 = __shfl_down_sync(0xffffffffu, pp1, 1);
        if (lane == 31)
            dp1 = (r < NP-1 && col < NP-1) ? base[(size_t)(r+1) * NP + col + 1] : 0.f;
        float v = p0 + um1 + dp1;
        float l = v * (g_eq[r] * SCALEF);
        if (l > mx) { sm = sm * expf(mx - l) + 1.f; mx = l; }
        else        { sm += expf(l - mx); }
        pm1 = p0; p0 = pp1;
        pp1 = (r + 2 < NP) ? base[(size_t)(r+2) * NP + col] : 0.f;
    }
    g_pmax[((size_t)b * 32 + chunk) * NP + col] = mx;
    g_psum[((size_t)b * 32 + chunk) * NP + col] = sm;
}

__global__ void k_smax2() {
    int idx = blockIdx.x * blockDim.x + threadIdx.x;
    if (idx >= BT * NP) return;
    int b = idx / NP, col = idx % NP;
    float M = -1e30f;
    for (int i = 0; i < 32; i++)
        M = fmaxf(M, g_pmax[((size_t)b * 32 + i) * NP + col]);
    float S = 0.f;
    for (int i = 0; i < 32; i++)
        S += g_psum[((size_t)b * 32 + i) * NP + col] *
             expf(g_pmax[((size_t)b * 32 + i) * NP + col] - M);
    g_cmax[idx] = M;
    g_csum[idx] = S;
    g_lthr[idx] = M + logf(SEL_THR * S);
}

// ===================== sparse selection (chunk-skip via pmax) ===============
__global__ void k_sel(const float* __restrict__ in) {
    int col = blockIdx.x * 256 + threadIdx.x;    // p
    int chunk = blockIdx.y;
    int b = blockIdx.z;
    int lane = threadIdx.x & 31;

    float lth = g_lthr[b*NP + col];
    int ccidx = (b*NP + col) * 32 + chunk;
    // exact skip: chunk max of the identical logit expression <= threshold
    // => no row in this chunk can be selected.
    bool skip = g_pmax[((size_t)b * 32 + chunk) * NP + col] <= lth;
    if (__all_sync(0xffffffffu, skip)) {
        g_ccnt[ccidx] = 0;
        return;
    }

    const float* base = in + (size_t)b * NP * NP;
    int r0 = chunk * 128;
    float M   = g_cmax[b*NP + col];
    float Sin = 1.f / g_csum[b*NP + col];

    float pm1 = (r0 > 0) ? base[(size_t)(r0-1) * NP + col] : 0.f;
    float p0  = base[(size_t)r0 * NP + col];
    float pp1 = (r0 + 1 < NP) ? base[(size_t)(r0+1) * NP + col] : 0.f;

    int s = 0;
    size_t slotbase = (((size_t)(b*NP + col)) * 32 + chunk) * SLOTS;
    for (int r = r0; r < r0 + 128; r++) {
        float um1 = __shfl_up_sync(0xffffffffu, pm1, 1);
        if (lane == 0)
            um1 = (r > 0 && col > 0) ? base[(size_t)(r-1) * NP + col - 1] : 0.f;
        float dp1 = __shfl_down_sync(0xffffffffu, pp1, 1);
        if (lane == 31)
            dp1 = (r < NP-1 && col < NP-1) ? base[(size_t)(r+1) * NP + col + 1] : 0.f;
        float v = p0 + um1 + dp1;
        float eqv = g_eq[r];
        float l = v * (eqv * SCALEF);
        if (l > lth && eqv != 0.f && s < SLOTS) {
            g_cidx[slotbase + s] = r;
            g_cwgt[slotbase + s] = expf(l - M) * Sin * eqv;
            s++;
        }
        pm1 = p0; p0 = pp1;
        pp1 = (r + 2 < NP) ? base[(size_t)(r+2) * NP + col] : 0.f;
    }
    g_ccnt[ccidx] = s;
}

__global__ void k_merge() {
    int idx = blockIdx.x * blockDim.x + threadIdx.x;
    if (idx >= BT * NP) return;
    int cnt = 0;
    size_t ob = (size_t)idx * KMAX;
    for (int ch = 0; ch < 32; ch++) {
        int c = g_ccnt[idx * 32 + ch];
        size_t sb = (((size_t)idx) * 32 + ch) * SLOTS;
        for (int i = 0; i < c && cnt < KMAX; i++) {
            g_midx[ob + cnt] = g_cidx[sb + i];
            g_mwgt[ob + cnt] = g_cwgt[sb + i];
            cnt++;
        }
    }
    g_mcnt[idx] = cnt;
}

// ===================== sparse apply + transposed-conv gather ================
__global__ void k_apply() {
    int wid = threadIdx.x >> 5, lane = threadIdx.x & 31;
    int P = blockIdx.x * 8 + wid;
    int b = blockIdx.y;
    int Y = P >> 7, X = P & 127;
    const __half* bgc = g_bgcl + (size_t)b * HWF * CC;
    float4 acc = make_float4(0.f, 0.f, 0.f, 0.f);
#pragma unroll
    for (int di = 0; di < 4; di++) {
        int ty = Y + 1 - di;
        if (ty < 0 || (ty & 1)) continue;
        int my = ty >> 1;
        if (my >= HS) continue;
#pragma unroll
        for (int dj = 0; dj < 4; dj++) {
            int tx = X + 1 - dj;
            if (tx < 0 || (tx & 1)) continue;
            int mx = tx >> 1;
            if (mx >= HS) continue;
            int p = my * 64 + mx;
            int lb = b * NP + p;
            int cnt = g_mcnt[lb];
            const int*   il = g_midx + (size_t)lb * KMAX;
            const float* wl = g_mwgt + (size_t)lb * KMAX;
            for (int i = 0; i < cnt; i++) {
                int m = il[i];
                float w = wl[i];
                int miy = m >> 6, mix = m & 63;
                int Ys = 2*miy + di - 1, Xs = 2*mix + dj - 1;
                if ((unsigned)Ys >= HH || (unsigned)Xs >= WW) continue;
                union { uint2 u; __half2 h[2]; } v;
                v.u = *(const uint2*)(bgc + ((size_t)(Ys * WW + Xs)) * CC + lane * 4);
                float2 a0 = __half22float2(v.h[0]);
                float2 a1 = __half22float2(v.h[1]);
                acc.x += w * a0.x; acc.y += w * a0.y;
                acc.z += w * a1.x; acc.w += w * a1.y;
            }
        }
    }
    union { __half2 h[2]; uint2 u; } cv;
    cv.h[0] = __floats2half2_rn(acc.x * 0.25f, acc.y * 0.25f);
    cv.h[1] = __floats2half2_rn(acc.z * 0.25f, acc.w * 0.25f);
    *(uint2*)(g_y16 + ((size_t)b * HWF + P) * CC + lane * 4) = cv.u;
}

// ===================== host orchestration =====================
extern "C" void kernel_launch(void* const* d_in, const int* in_sizes, int n_in,
                              void* d_out, int out_size) {
    const float* fg   = (const float*)d_in[0];
    const float* bg   = (const float*)d_in[1];
    const float* mask = (const float*)d_in[2];
    const float* w1   = (const float*)d_in[3];
    const float* b1   = (const float*)d_in[4];
    const float* w2   = (const float*)d_in[5];
    const float* b2   = (const float*)d_in[6];
    float* out = (float*)d_out;

    cudaFuncSetAttribute(mgemm, cudaFuncAttributeMaxDynamicSharedMemorySize, MGEMM_SMEM);
    cudaFuncSetAttribute(cgemm<0>, cudaFuncAttributeMaxDynamicSharedMemorySize, CGEMM_SMEM);
    cudaFuncSetAttribute(cgemm<1>, cudaFuncAttributeMaxDynamicSharedMemorySize, CGEMM_SMEM);

    __nv_bfloat16 *bh, *bl, *fh, *fl;
    __half *y16, *h16, *w1h, *w1l, *w2h, *w2l;
    float *bufA, *bufB;
    cudaGetSymbolAddress((void**)&bh, g_bh);     cudaGetSymbolAddress((void**)&bl, g_bl);
    cudaGetSymbolAddress((void**)&fh, g_fh);     cudaGetSymbolAddress((void**)&fl, g_fl);
    cudaGetSymbolAddress((void**)&y16, g_y16);   cudaGetSymbolAddress((void**)&h16, g_h16);
    cudaGetSymbolAddress((void**)&w1h, g_w1h16); cudaGetSymbolAddress((void**)&w1l, g_w1l16);
    cudaGetSymbolAddress((void**)&w2h, g_w2h16); cudaGetSymbolAddress((void**)&w2l, g_w2l16);
    cudaGetSymbolAddress((void**)&bufA, g_bufA);
    cudaGetSymbolAddress((void**)&bufB, g_bufB);

    // prep
    k_half    <<<(BT*NP*CC + 255)/256, 256>>>(bg, bh, bl);
    k_half    <<<(BT*NP*CC + 255)/256, 256>>>(fg, fh, fl);
    k_ss      <<<(BT*NP + 255)/256, 256>>>();
    k_inv     <<<(BT*NP + 255)/256, 256>>>();
    k_bgcl    <<<dim3(HWF/32, CC/32, BT), 256>>>(bg);
    k_eq      <<<16, 256>>>(mask);
    k_wreorder<<<(CC*K1 + 255)/256, 256>>>(w1, w1h, w1l);
    k_wreorder<<<(CC*K1 + 255)/256, 256>>>(w2, w2h, w2l);

    // GEMM1: G[u][v] = sum_c b[u][c] f[v][c]  (bf16 3-term) -> bufA
    mgemm<<<dim3(32, 32, BT), 256, MGEMM_SMEM>>>(
        bh, bl, fh, fl, bufA, CC, NP,
        (size_t)NP * CC, (size_t)NP * CC, (size_t)NP * NP);

    // scores = 9-tap diagonal stencil / norm -> bufB
    k_stencil9<<<BT * 4096, 256>>>(bufA, bufB);

    // fuse1 + permutation -> bufA
    k_fuseperm<<<BT * NP, 256>>>(bufB, bufA);

    // fuse2 on-the-fly + softmax stats
    k_smax1<<<dim3(16, 32, BT), 256>>>(bufA);
    k_smax2<<<32, 256>>>();

    // sparse selection (chunk-skip) + merge
    k_sel  <<<dim3(16, 32, BT), 256>>>(bufA);
    k_merge<<<32, 256>>>();

    // sparse attention apply + transposed-conv gather -> y16
    k_apply<<<dim3(HWF/8, BT), 256>>>();

    // conv1 + ELU (implicit, fp16 2-term W) -> h16 image
    cgemm<1><<<dim3(HWF/256, 1, BT), 256, CGEMM_SMEM>>>(
        w1h, w1l, y16, nullptr, h16, b1);

    // conv2 + ELU (implicit) -> out fp32 NCHW
    cgemm<0><<<dim3(HWF/256, 1, BT), 256, CGEMM_SMEM>>>(
        w2h, w2l, h16, out, nullptr, b2);
}

// round 13
// speedup vs baseline: 1.2485x; 1.1201x over previous
#include <cuda_runtime.h>
#include <cuda_bf16.h>
#include <cuda_fp16.h>
#include <math.h>
#include <stdint.h>

#define BT 2
#define CC 128
#define HH 128
#define WW 128
#define HS 64
#define NP 4096
#define K1 1152
#define HWF 16384
#define SCALEF 10.0f
#define SEL_THR 1e-7f
#define SLOTS 16
#define KMAX 128

// ===================== scratch =====================
__device__ __align__(256) __nv_bfloat16 g_bh [(size_t)BT*NP*CC];
__device__ __align__(256) __nv_bfloat16 g_bl [(size_t)BT*NP*CC];
__device__ __align__(256) __nv_bfloat16 g_fh [(size_t)BT*NP*CC];
__device__ __align__(256) __nv_bfloat16 g_fl [(size_t)BT*NP*CC];
__device__ __align__(256) __half        g_bgcl[(size_t)BT*HWF*CC]; // bg channels-last fp16
__device__ __align__(256) __half        g_y16 [(size_t)BT*HWF*CC]; // y image channels-last
__device__ __align__(256) __half        g_h16 [(size_t)BT*HWF*CC]; // h image channels-last
__device__ __align__(256) __half        g_w116[CC*K1];
__device__ __align__(256) __half        g_w216[CC*K1];
__device__ __align__(256) float g_bufA[(size_t)BT*NP*NP];
__device__ __align__(256) float g_bufB[(size_t)BT*NP*NP];
__device__ int   g_cidx[(size_t)BT*NP*32*SLOTS];
__device__ float g_cwgt[(size_t)BT*NP*32*SLOTS];
__device__ int   g_ccnt[BT*NP*32];
__device__ int   g_midx[(size_t)BT*NP*KMAX];
__device__ float g_mwgt[(size_t)BT*NP*KMAX];
__device__ int   g_mcnt[BT*NP];
__device__ float g_eq  [NP];
__device__ float g_ss  [BT*NP];
__device__ float g_inv [BT*NP];
__device__ float g_pmax[BT*32*NP];
__device__ float g_psum[BT*32*NP];
__device__ float g_cmax[BT*NP];
__device__ float g_csum[BT*NP];
__device__ float g_lthr[BT*NP];

__device__ __forceinline__ void split_store(__nv_bfloat16* H, __nv_bfloat16* L,
                                            size_t idx, float v) {
    __nv_bfloat16 h = __float2bfloat16(v);
    H[idx] = h;
    L[idx] = __float2bfloat16(v - __bfloat162float(h));
}
__device__ __forceinline__ uint32_t smem_u32(const void* p) {
    uint32_t a;
    asm("{ .reg .u64 t; cvta.to.shared.u64 t, %1; cvt.u32.u64 %0, t; }" : "=r"(a) : "l"(p));
    return a;
}
__device__ __forceinline__ void ldsm_x4(uint32_t (&r)[4], uint32_t addr) {
    asm volatile("ldmatrix.sync.aligned.m8n8.x4.shared.b16 {%0,%1,%2,%3}, [%4];"
                 : "=r"(r[0]), "=r"(r[1]), "=r"(r[2]), "=r"(r[3]) : "r"(addr));
}
__device__ __forceinline__ void mma_bf16(float (&d)[4], const uint32_t (&a)[4],
                                         uint32_t b0, uint32_t b1) {
    asm volatile("mma.sync.aligned.m16n8k16.row.col.f32.bf16.bf16.f32 "
        "{%0,%1,%2,%3}, {%4,%5,%6,%7}, {%8,%9}, {%0,%1,%2,%3};"
        : "+f"(d[0]), "+f"(d[1]), "+f"(d[2]), "+f"(d[3])
        : "r"(a[0]), "r"(a[1]), "r"(a[2]), "r"(a[3]), "r"(b0), "r"(b1));
}
__device__ __forceinline__ void mma_f16(float (&d)[4], const uint32_t (&a)[4],
                                        uint32_t b0, uint32_t b1) {
    asm volatile("mma.sync.aligned.m16n8k16.row.col.f32.f16.f16.f32 "
        "{%0,%1,%2,%3}, {%4,%5,%6,%7}, {%8,%9}, {%0,%1,%2,%3};"
        : "+f"(d[0]), "+f"(d[1]), "+f"(d[2]), "+f"(d[3])
        : "r"(a[0]), "r"(a[1]), "r"(a[2]), "r"(a[3]), "r"(b0), "r"(b1));
}
__device__ __forceinline__ void cpasync16(uint32_t saddr, const void* g) {
    asm volatile("cp.async.cg.shared.global [%0], [%1], 16;" :: "r"(saddr), "l"(g));
}
__device__ __forceinline__ void cpasync16z(uint32_t saddr, const void* g, int szbytes) {
    asm volatile("cp.async.cg.shared.global [%0], [%1], 16, %2;"
                 :: "r"(saddr), "l"(g), "r"(szbytes));
}

// ===================== prep =====================
__global__ void k_half(const float* __restrict__ src, __nv_bfloat16* H, __nv_bfloat16* L) {
    int idx = blockIdx.x * blockDim.x + threadIdx.x;
    if (idx >= BT * NP * CC) return;
    int c = idx & 127;
    int t = idx >> 7;
    int n = t & 4095;
    int b = t >> 12;
    int y = n >> 6, x = n & 63;
    float v = src[(((size_t)b*CC + c)*HH + 2*y)*WW + 2*x];
    split_store(H, L, (size_t)idx, v);
}

__global__ void k_ss() {
    int idx = blockIdx.x * blockDim.x + threadIdx.x;
    if (idx >= BT * NP) return;
    const __nv_bfloat162* h2 = (const __nv_bfloat162*)(g_bh + (size_t)idx * CC);
    const __nv_bfloat162* l2 = (const __nv_bfloat162*)(g_bl + (size_t)idx * CC);
    float s = 0.f;
#pragma unroll
    for (int c = 0; c < CC/2; c++) {
        float2 a = __bfloat1622float2(h2[c]);
        float2 bb = __bfloat1622float2(l2[c]);
        float v0 = a.x + bb.x, v1 = a.y + bb.y;
        s += v0*v0 + v1*v1;
    }
    g_ss[idx] = s;
}

__global__ void k_inv() {
    int idx = blockIdx.x * blockDim.x + threadIdx.x;
    if (idx >= BT * NP) return;
    int b = idx >> 12, n = idx & 4095;
    int ny = n >> 6, nx = n & 63;
    float s = 0.f;
#pragma unroll
    for (int i = 0; i < 3; i++)
#pragma unroll
        for (int j = 0; j < 3; j++) {
            int y = ny + i - 1, x = nx + j - 1;
            if ((unsigned)y < 64u && (unsigned)x < 64u)
                s += g_ss[b*NP + y*64 + x];
        }
    g_inv[idx] = 1.f / fmaxf(sqrtf(s), 1e-4f);
}

__global__ void k_bgcl(const float* __restrict__ bg) {
    __shared__ float tile[32][33];
    int b = blockIdx.z;
    int c0 = blockIdx.y * 32;
    int p0 = blockIdx.x * 32;
    int tx = threadIdx.x & 31, ty = threadIdx.x >> 5;
#pragma unroll
    for (int k = 0; k < 4; k++) {
        int c = c0 + ty + k*8;
        tile[ty + k*8][tx] = bg[((size_t)(b*CC + c))*HWF + p0 + tx];
    }
    __syncthreads();
#pragma unroll
    for (int k = 0; k < 4; k++) {
        int p = p0 + ty + k*8;
        g_bgcl[((size_t)(b*HWF + p))*CC + c0 + tx] = __float2half(tile[tx][ty + k*8]);
    }
}

__global__ void k_eq(const float* __restrict__ mask) {
    int n = blockIdx.x * blockDim.x + threadIdx.x;
    if (n >= NP) return;
    int ny = n / HS, nx = n % HS;
    float s = 0.f;
#pragma unroll
    for (int i = 0; i < 3; i++)
#pragma unroll
        for (int j = 0; j < 3; j++) {
            int y = ny + i - 1, x = nx + j - 1;
            if ((unsigned)y < HS && (unsigned)x < HS)
                s += mask[(2*y)*WW + 2*x];
        }
    g_eq[n] = ((s / 9.f) == 0.f) ? 1.f : 0.f;
}

// weight reorder: out[r][tap*128+c] = w[r][c*9+tap], single fp16
__global__ void k_wreorder(const float* __restrict__ w, __half* H) {
    int idx = blockIdx.x * blockDim.x + threadIdx.x;
    if (idx >= CC * K1) return;
    int r = idx / K1;
    int rem = idx % K1;
    int tap = rem >> 7;
    int c = rem & 127;
    H[idx] = __float2half(w[r * K1 + c * 9 + tap]);
}

// ===================== bf16-split GEMM (3-term, 128x128) — GEMM1 =============
#define KT 32
#define STAGES 3
#define STAGE_BYTES (4*128*KT*2)
#define MGEMM_SMEM (STAGES*STAGE_BYTES)

__global__ void __launch_bounds__(256, 1) mgemm(
    const __nv_bfloat16* __restrict__ Ah, const __nv_bfloat16* __restrict__ Al,
    const __nv_bfloat16* __restrict__ Bh, const __nv_bfloat16* __restrict__ Bl,
    float* __restrict__ C, int K, int N,
    size_t sA, size_t sB, size_t sC)
{
    extern __shared__ char sm[];
    const uint32_t smb = smem_u32(sm);
    const int tid = threadIdx.x;
    const int bz = blockIdx.z;
    const int bm = blockIdx.y * 128;
    const int bn = blockIdx.x * 128;
    C += sC * bz;

    const int j   = tid >> 6;
    const int l64 = tid & 63;
    const int rbase = (j < 2) ? bm : bn;
    const __nv_bfloat16* src =
        (j == 0) ? Ah + sA*bz : (j == 1) ? Al + sA*bz : (j == 2) ? Bh + sB*bz : Bl + sB*bz;

    const int NC = K >> 5;

#pragma unroll
    for (int s = 0; s < STAGES - 1; s++) {
        const int kc = s * KT;
#pragma unroll
        for (int i = 0; i < 8; i++) {
            int id = l64 + i * 64;
            int row = id >> 2, ch = id & 3;
            const void* g = src + (size_t)(rbase + row) * K + kc + ch * 8;
            uint32_t sa = smb + s*STAGE_BYTES + j*8192 + row*64 + ((ch ^ ((row >> 1) & 3)) << 4);
            cpasync16(sa, g);
        }
        asm volatile("cp.async.commit_group;");
    }

    const int wid = tid >> 5, lane = tid & 31;
    const int wm = wid & 1, wn = wid >> 1;

    float acc[4][4][4];
#pragma unroll
    for (int a = 0; a < 4; a++)
#pragma unroll
        for (int bb = 0; bb < 4; bb++)
#pragma unroll
            for (int c = 0; c < 4; c++) acc[a][bb][c] = 0.f;

    for (int i = 0; i < NC; i++) {
        asm volatile("cp.async.wait_group 1;");
        __syncthreads();

        if (i + STAGES - 1 < NC) {
            const int s2 = (i + STAGES - 1) % STAGES;
            const int kc = (i + STAGES - 1) * KT;
#pragma unroll
            for (int it = 0; it < 8; it++) {
                int id = l64 + it * 64;
                int row = id >> 2, ch = id & 3;
                const void* g = src + (size_t)(rbase + row) * K + kc + ch * 8;
                uint32_t sa = smb + s2*STAGE_BYTES + j*8192 + row*64 + ((ch ^ ((row >> 1) & 3)) << 4);
                cpasync16(sa, g);
            }
        }
        asm volatile("cp.async.commit_group;");

        const uint32_t stb = smb + (i % STAGES) * STAGE_BYTES;
#pragma unroll
        for (int h = 0; h < 2; h++) {
            uint32_t ah[4][4], al[4][4];
            uint32_t bh[4][2], bl[4][2];
#pragma unroll
            for (int tm = 0; tm < 4; tm++) {
                int row = wm*64 + tm*16 + (lane & 15);
                int ch  = 2*h + (lane >> 4);
                uint32_t ad = stb + row*64 + ((ch ^ ((row >> 1) & 3)) << 4);
                ldsm_x4(ah[tm], ad);
                ldsm_x4(al[tm], ad + 8192);
            }
#pragma unroll
            for (int tp = 0; tp < 2; tp++) {
                int row = wn*32 + tp*16 + ((lane >> 4) << 3) + (lane & 7);
                int ch  = 2*h + ((lane >> 3) & 1);
                uint32_t bd = stb + 16384 + row*64 + ((ch ^ ((row >> 1) & 3)) << 4);
                uint32_t r[4];
                ldsm_x4(r, bd);
                bh[tp*2][0] = r[0]; bh[tp*2][1] = r[1];
                bh[tp*2+1][0] = r[2]; bh[tp*2+1][1] = r[3];
                ldsm_x4(r, bd + 8192);
                bl[tp*2][0] = r[0]; bl[tp*2][1] = r[1];
                bl[tp*2+1][0] = r[2]; bl[tp*2+1][1] = r[3];
            }
#pragma unroll
            for (int tm = 0; tm < 4; tm++)
#pragma unroll
                for (int tn = 0; tn < 4; tn++) {
                    mma_bf16(acc[tm][tn], ah[tm], bh[tn][0], bh[tn][1]);
                    mma_bf16(acc[tm][tn], ah[tm], bl[tn][0], bl[tn][1]);
                    mma_bf16(acc[tm][tn], al[tm], bh[tn][0], bh[tn][1]);
                }
        }
    }

#pragma unroll
    for (int tm = 0; tm < 4; tm++) {
        int row = bm + wm*64 + tm*16 + (lane >> 2);
#pragma unroll
        for (int hf = 0; hf < 2; hf++) {
            int r = row + hf*8;
            float* dst = C + (size_t)r * N + bn + wn*32 + (lane & 3)*2;
#pragma unroll
            for (int tn = 0; tn < 4; tn++)
                *(float2*)(dst + tn*8) = make_float2(acc[tm][tn][hf*2+0], acc[tm][tn][hf*2+1]);
        }
    }
}

// ===================== implicit conv GEMM: 128ch x 256pix, fp16 1-term W =====
#define CSTAGE (8192 + 16384)
#define CGEMM_SMEM (STAGES*CSTAGE)
#define TPITCH 136

template<int OUT16>
__global__ void __launch_bounds__(256, 1) cgemm(
    const __half* __restrict__ Wh,
    const __half* __restrict__ img,
    float* __restrict__ Cout, __half* __restrict__ out16,
    const float* __restrict__ bias)
{
    extern __shared__ char sm[];
    const uint32_t smb = smem_u32(sm);
    const int tid = threadIdx.x;
    const int bz = blockIdx.z;
    const int bn = blockIdx.x * 256;
    const __half* ib = img + (size_t)bz * HWF * CC;

    const int NC = K1 >> 5;   // 36

    auto load_stage = [&](int s, int kc) {
        // weights: 128 rows x 32 halves = 512 16B chunks / 256 threads
#pragma unroll
        for (int it = 0; it < 2; it++) {
            int id = tid + it * 256;
            int row = id >> 2, ch = id & 3;
            uint32_t swz = (uint32_t)(row * 64 + ((ch ^ ((row >> 1) & 3)) << 4));
            cpasync16(smb + s*CSTAGE + swz, Wh + (size_t)row * K1 + kc + ch * 8);
        }
        int tap = kc >> 7;
        int ki = tap / 3, kj = tap - ki * 3;
        int c0 = kc & 127;
#pragma unroll
        for (int it = 0; it < 4; it++) {
            int id = tid + it * 256;
            int row = id >> 2, ch = id & 3;
            int p = bn + row;
            int Y = (p >> 7) + ki - 1, X = (p & 127) + kj - 1;
            bool ok = (unsigned)Y < HH && (unsigned)X < WW;
            const __half* g = ok ? ib + ((size_t)(Y * WW + X)) * CC + c0 + ch * 8 : ib;
            uint32_t swz = (uint32_t)(row * 64 + ((ch ^ ((row >> 1) & 3)) << 4));
            cpasync16z(smb + s*CSTAGE + 8192 + swz, g, ok ? 16 : 0);
        }
        asm volatile("cp.async.commit_group;");
    };

#pragma unroll
    for (int s = 0; s < STAGES - 1; s++) load_stage(s, s * KT);

    const int wid = tid >> 5, lane = tid & 31;
    const int wm = wid & 1, wn = wid >> 1;

    float acc[4][8][4];
#pragma unroll
    for (int a = 0; a < 4; a++)
#pragma unroll
        for (int bb = 0; bb < 8; bb++)
#pragma unroll
            for (int c = 0; c < 4; c++) acc[a][bb][c] = 0.f;

    for (int i = 0; i < NC; i++) {
        asm volatile("cp.async.wait_group 1;");
        __syncthreads();

        if (i + STAGES - 1 < NC)
            load_stage((i + STAGES - 1) % STAGES, (i + STAGES - 1) * KT);
        else
            asm volatile("cp.async.commit_group;");

        const uint32_t stb = smb + (i % STAGES) * CSTAGE;
#pragma unroll
        for (int h = 0; h < 2; h++) {
            uint32_t ah[4][4];
            uint32_t bf[8][2];
#pragma unroll
            for (int tm = 0; tm < 4; tm++) {
                int row = wm*64 + tm*16 + (lane & 15);
                int ch  = 2*h + (lane >> 4);
                uint32_t ad = stb + row*64 + ((ch ^ ((row >> 1) & 3)) << 4);
                ldsm_x4(ah[tm], ad);
            }
#pragma unroll
            for (int tb = 0; tb < 4; tb++) {
                int row = wn*64 + tb*16 + ((lane >> 4) << 3) + (lane & 7);
                int ch  = 2*h + ((lane >> 3) & 1);
                uint32_t bd = stb + 8192 + row*64 + ((ch ^ ((row >> 1) & 3)) << 4);
                uint32_t r[4];
                ldsm_x4(r, bd);
                bf[tb*2][0] = r[0]; bf[tb*2][1] = r[1];
                bf[tb*2+1][0] = r[2]; bf[tb*2+1][1] = r[3];
            }
#pragma unroll
            for (int tm = 0; tm < 4; tm++)
#pragma unroll
                for (int tn = 0; tn < 8; tn++)
                    mma_f16(acc[tm][tn], ah[tm], bf[tn][0], bf[tn][1]);
        }
    }

    if (OUT16) {
        asm volatile("cp.async.wait_group 0;");
        __syncthreads();
        __half* st = (__half*)sm;
#pragma unroll
        for (int tm = 0; tm < 4; tm++) {
#pragma unroll
            for (int hf = 0; hf < 2; hf++) {
                int r = wm*64 + tm*16 + (lane >> 2) + hf*8;
                float bv = bias[r];
#pragma unroll
                for (int tn = 0; tn < 8; tn++) {
                    int col = wn*64 + tn*8 + (lane & 3)*2;
                    float x0 = acc[tm][tn][hf*2+0] + bv;
                    float x1 = acc[tm][tn][hf*2+1] + bv;
                    x0 = x0 > 0.f ? x0 : expf(x0) - 1.f;
                    x1 = x1 > 0.f ? x1 : expf(x1) - 1.f;
                    st[(size_t)col * TPITCH + r]       = __float2half(x0);
                    st[(size_t)(col+1) * TPITCH + r]   = __float2half(x1);
                }
            }
        }
        __syncthreads();
        __half* dst = out16 + ((size_t)bz * HWF + bn + tid) * CC;
        const uint4* srcv = (const uint4*)(st + (size_t)tid * TPITCH);
#pragma unroll
        for (int i = 0; i < 16; i++)
            ((uint4*)dst)[i] = srcv[i];
    } else {
        float* C = Cout + (size_t)bz * CC * HWF;
#pragma unroll
        for (int tm = 0; tm < 4; tm++) {
            int row = wm*64 + tm*16 + (lane >> 2);
#pragma unroll
            for (int hf = 0; hf < 2; hf++) {
                int r = row + hf*8;
                float bv = bias[r];
                float* dst = C + (size_t)r * HWF + bn + wn*64 + (lane & 3)*2;
#pragma unroll
                for (int tn = 0; tn < 8; tn++) {
                    float x0 = acc[tm][tn][hf*2+0] + bv;
                    float x1 = acc[tm][tn][hf*2+1] + bv;
                    x0 = x0 > 0.f ? x0 : expf(x0) - 1.f;
                    x1 = x1 > 0.f ? x1 : expf(x1) - 1.f;
                    *(float2*)(dst + tn*8) = make_float2(x0, x1);
                }
            }
        }
    }
}

// ===================== stencil =====================
__global__ void __launch_bounds__(256) k_stencil9(const float* __restrict__ G,
                                                  float* __restrict__ out) {
    __shared__ float t3[3][64][64];
    int bid = blockIdx.x;
    int b = bid >> 12;
    int rest = bid & 4095;
    int ny = rest >> 6, py = rest & 63;
    const float* Gb = G + (size_t)b * NP * NP;
    float* ob = out + (size_t)b * NP * NP;
    int tid = threadIdx.x;

#pragma unroll
    for (int dy = 0; dy < 3; dy++) {
        int gy = ny + dy - 1, gpy = py + dy - 1;
        bool ok = (unsigned)gy < 64 && (unsigned)gpy < 64;
        for (int idx = tid; idx < 4096; idx += 256) {
            int i = idx >> 6, jj = idx & 63;
            t3[dy][i][jj] = ok ? Gb[((size_t)(gy*64 + i)) * NP + gpy*64 + jj] : 0.f;
        }
    }
    __syncthreads();

    int px = tid & 63;
    int nx0 = tid >> 6;
    for (int nx = nx0; nx < 64; nx += 4) {
        float s = 0.f;
#pragma unroll
        for (int dy = 0; dy < 3; dy++)
#pragma unroll
            for (int dx = -1; dx <= 1; dx++) {
                int a = nx + dx, c = px + dx;
                if ((unsigned)a < 64 && (unsigned)c < 64)
                    s += t3[dy][a][c];
            }
        ob[((size_t)(ny*64 + nx)) * NP + py*64 + px] = s * g_inv[b*NP + ny*64 + nx];
    }
}

// ===================== fuse1 + permutation =====================
__global__ void k_fuseperm(const float* __restrict__ in, float* __restrict__ out) {
    __shared__ float tile[64 * 65];
    int brow = blockIdx.x;
    int b = brow / NP, rp = brow % NP;
    int nx = rp >> 6, ny = rp & 63;
    int r = ny * 64 + nx;
    const float* src = in + (size_t)b * NP * NP;
    float*       dst = out + ((size_t)b * NP + rp) * NP;
    int tid = threadIdx.x;
    for (int k = tid; k < NP; k += 256) {
        float f = src[(size_t)r * NP + k];
        if (r > 0 && k > 0)           f += src[(size_t)(r-1) * NP + k - 1];
        if (r < NP-1 && k < NP-1)     f += src[(size_t)(r+1) * NP + k + 1];
        tile[(k & 63) * 65 + (k >> 6)] = f;
    }
    __syncthreads();
    for (int j = tid; j < NP; j += 256)
        dst[j] = tile[(j >> 6) * 65 + (j & 63)];
}

// ===================== softmax stats (fuse2 on the fly) =====================
__global__ void k_smax1(const float* __restrict__ in) {
    int col = blockIdx.x * 256 + threadIdx.x;
    int chunk = blockIdx.y;
    int b = blockIdx.z;
    int lane = threadIdx.x & 31;
    const float* base = in + (size_t)b * NP * NP;
    int r0 = chunk * 128;

    float pm1 = (r0 > 0) ? base[(size_t)(r0-1) * NP + col] : 0.f;
    float p0  = base[(size_t)r0 * NP + col];
    float pp1 = (r0 + 1 < NP) ? base[(size_t)(r0+1) * NP + col] : 0.f;

    float mx = -1e30f, sm = 0.f;
    for (int r = r0; r < r0 + 128; r++) {
        float um1 = __shfl_up_sync(0xffffffffu, pm1, 1);
        if (lane == 0)
            um1 = (r > 0 && col > 0) ? base[(size_t)(r-1) * NP + col - 1] : 0.f;
        float dp1 = __shfl_down_sync(0xffffffffu, pp1, 1);
        if (lane == 31)
            dp1 = (r < NP-1 && col < NP-1) ? base[(size_t)(r+1) * NP + col + 1] : 0.f;
        float v = p0 + um1 + dp1;
        float l = v * (g_eq[r] * SCALEF);
        if (l > mx) { sm = sm * expf(mx - l) + 1.f; mx = l; }
        else        { sm += expf(l - mx); }
        pm1 = p0; p0 = pp1;
        pp1 = (r + 2 < NP) ? base[(size_t)(r+2) * NP + col] : 0.f;
    }
    g_pmax[((size_t)b * 32 + chunk) * NP + col] = mx;
    g_psum[((size_t)b * 32 + chunk) * NP + col] = sm;
}

__global__ void k_smax2() {
    int idx = blockIdx.x * blockDim.x + threadIdx.x;
    if (idx >= BT * NP) return;
    int b = idx / NP, col = idx % NP;
    float M = -1e30f;
    for (int i = 0; i < 32; i++)
        M = fmaxf(M, g_pmax[((size_t)b * 32 + i) * NP + col]);
    float S = 0.f;
    for (int i = 0; i < 32; i++)
        S += g_psum[((size_t)b * 32 + i) * NP + col] *
             expf(g_pmax[((size_t)b * 32 + i) * NP + col] - M);
    g_cmax[idx] = M;
    g_csum[idx] = S;
    g_lthr[idx] = M + logf(SEL_THR * S);
}

// ===================== sparse selection (R10 exact) =========================
__global__ void k_sel(const float* __restrict__ in) {
    int col = blockIdx.x * 256 + threadIdx.x;    // p
    int chunk = blockIdx.y;
    int b = blockIdx.z;
    int lane = threadIdx.x & 31;
    const float* base = in + (size_t)b * NP * NP;
    int r0 = chunk * 128;

    float lth = g_lthr[b*NP + col];
    float M   = g_cmax[b*NP + col];
    float Sin = 1.f / g_csum[b*NP + col];

    float pm1 = (r0 > 0) ? base[(size_t)(r0-1) * NP + col] : 0.f;
    float p0  = base[(size_t)r0 * NP + col];
    float pp1 = (r0 + 1 < NP) ? base[(size_t)(r0+1) * NP + col] : 0.f;

    int s = 0;
    size_t slotbase = (((size_t)(b*NP + col)) * 32 + chunk) * SLOTS;
    for (int r = r0; r < r0 + 128; r++) {
        float um1 = __shfl_up_sync(0xffffffffu, pm1, 1);
        if (lane == 0)
            um1 = (r > 0 && col > 0) ? base[(size_t)(r-1) * NP + col - 1] : 0.f;
        float dp1 = __shfl_down_sync(0xffffffffu, pp1, 1);
        if (lane == 31)
            dp1 = (r < NP-1 && col < NP-1) ? base[(size_t)(r+1) * NP + col + 1] : 0.f;
        float v = p0 + um1 + dp1;
        float eqv = g_eq[r];
        float l = v * (eqv * SCALEF);
        if (l > lth && eqv != 0.f && s < SLOTS) {
            g_cidx[slotbase + s] = r;
            g_cwgt[slotbase + s] = expf(l - M) * Sin * eqv;
            s++;
        }
        pm1 = p0; p0 = pp1;
        pp1 = (r + 2 < NP) ? base[(size_t)(r+2) * NP + col] : 0.f;
    }
    g_ccnt[(b*NP + col) * 32 + chunk] = s;
}

__global__ void k_merge() {
    int idx = blockIdx.x * blockDim.x + threadIdx.x;
    if (idx >= BT * NP) return;
    int cnt = 0;
    size_t ob = (size_t)idx * KMAX;
    for (int ch = 0; ch < 32; ch++) {
        int c = g_ccnt[idx * 32 + ch];
        size_t sb = (((size_t)idx) * 32 + ch) * SLOTS;
        for (int i = 0; i < c && cnt < KMAX; i++) {
            g_midx[ob + cnt] = g_cidx[sb + i];
            g_mwgt[ob + cnt] = g_cwgt[sb + i];
            cnt++;
        }
    }
    g_mcnt[idx] = cnt;
}

// ===================== sparse apply + transposed-conv gather ================
__global__ void k_apply() {
    int wid = threadIdx.x >> 5, lane = threadIdx.x & 31;
    int P = blockIdx.x * 8 + wid;
    int b = blockIdx.y;
    int Y = P >> 7, X = P & 127;
    const __half* bgc = g_bgcl + (size_t)b * HWF * CC;
    float4 acc = make_float4(0.f, 0.f, 0.f, 0.f);
#pragma unroll
    for (int di = 0; di < 4; di++) {
        int ty = Y + 1 - di;
        if (ty < 0 || (ty & 1)) continue;
        int my = ty >> 1;
        if (my >= HS) continue;
#pragma unroll
        for (int dj = 0; dj < 4; dj++) {
            int tx = X + 1 - dj;
            if (tx < 0 || (tx & 1)) continue;
            int mx = tx >> 1;
            if (mx >= HS) continue;
            int p = my * 64 + mx;
            int lb = b * NP + p;
            int cnt = g_mcnt[lb];
            const int*   il = g_midx + (size_t)lb * KMAX;
            const float* wl = g_mwgt + (size_t)lb * KMAX;
            for (int i = 0; i < cnt; i++) {
                int m = il[i];
                float w = wl[i];
                int miy = m >> 6, mix = m & 63;
                int Ys = 2*miy + di - 1, Xs = 2*mix + dj - 1;
                if ((unsigned)Ys >= HH || (unsigned)Xs >= WW) continue;
                union { uint2 u; __half2 h[2]; } v;
                v.u = *(const uint2*)(bgc + ((size_t)(Ys * WW + Xs)) * CC + lane * 4);
                float2 a0 = __half22float2(v.h[0]);
                float2 a1 = __half22float2(v.h[1]);
                acc.x += w * a0.x; acc.y += w * a0.y;
                acc.z += w * a1.x; acc.w += w * a1.y;
            }
        }
    }
    union { __half2 h[2]; uint2 u; } cv;
    cv.h[0] = __floats2half2_rn(acc.x * 0.25f, acc.y * 0.25f);
    cv.h[1] = __floats2half2_rn(acc.z * 0.25f, acc.w * 0.25f);
    *(uint2*)(g_y16 + ((size_t)b * HWF + P) * CC + lane * 4) = cv.u;
}

// ===================== host orchestration =====================
extern "C" void kernel_launch(void* const* d_in, const int* in_sizes, int n_in,
                              void* d_out, int out_size) {
    const float* fg   = (const float*)d_in[0];
    const float* bg   = (const float*)d_in[1];
    const float* mask = (const float*)d_in[2];
    const float* w1   = (const float*)d_in[3];
    const float* b1   = (const float*)d_in[4];
    const float* w2   = (const float*)d_in[5];
    const float* b2   = (const float*)d_in[6];
    float* out = (float*)d_out;

    cudaFuncSetAttribute(mgemm, cudaFuncAttributeMaxDynamicSharedMemorySize, MGEMM_SMEM);
    cudaFuncSetAttribute(cgemm<0>, cudaFuncAttributeMaxDynamicSharedMemorySize, CGEMM_SMEM);
    cudaFuncSetAttribute(cgemm<1>, cudaFuncAttributeMaxDynamicSharedMemorySize, CGEMM_SMEM);

    __nv_bfloat16 *bh, *bl, *fh, *fl;
    __half *y16, *h16, *w116, *w216;
    float *bufA, *bufB;
    cudaGetSymbolAddress((void**)&bh, g_bh);     cudaGetSymbolAddress((void**)&bl, g_bl);
    cudaGetSymbolAddress((void**)&fh, g_fh);     cudaGetSymbolAddress((void**)&fl, g_fl);
    cudaGetSymbolAddress((void**)&y16, g_y16);   cudaGetSymbolAddress((void**)&h16, g_h16);
    cudaGetSymbolAddress((void**)&w116, g_w116); cudaGetSymbolAddress((void**)&w216, g_w216);
    cudaGetSymbolAddress((void**)&bufA, g_bufA);
    cudaGetSymbolAddress((void**)&bufB, g_bufB);

    // prep
    k_half    <<<(BT*NP*CC + 255)/256, 256>>>(bg, bh, bl);
    k_half    <<<(BT*NP*CC + 255)/256, 256>>>(fg, fh, fl);
    k_ss      <<<(BT*NP + 255)/256, 256>>>();
    k_inv     <<<(BT*NP + 255)/256, 256>>>();
    k_bgcl    <<<dim3(HWF/32, CC/32, BT), 256>>>(bg);
    k_eq      <<<16, 256>>>(mask);
    k_wreorder<<<(CC*K1 + 255)/256, 256>>>(w1, w116);
    k_wreorder<<<(CC*K1 + 255)/256, 256>>>(w2, w216);

    // GEMM1: G[u][v] = sum_c b[u][c] f[v][c]  (bf16 3-term) -> bufA
    mgemm<<<dim3(32, 32, BT), 256, MGEMM_SMEM>>>(
        bh, bl, fh, fl, bufA, CC, NP,
        (size_t)NP * CC, (size_t)NP * CC, (size_t)NP * NP);

    // scores = 9-tap diagonal stencil / norm -> bufB
    k_stencil9<<<BT * 4096, 256>>>(bufA, bufB);

    // fuse1 + permutation -> bufA
    k_fuseperm<<<BT * NP, 256>>>(bufB, bufA);

    // fuse2 on-the-fly + softmax stats
    k_smax1<<<dim3(16, 32, BT), 256>>>(bufA);
    k_smax2<<<32, 256>>>();

    // sparse selection + merge
    k_sel  <<<dim3(16, 32, BT), 256>>>(bufA);
    k_merge<<<32, 256>>>();

    // sparse attention apply + transposed-conv gather -> y16
    k_apply<<<dim3(HWF/8, BT), 256>>>();

    // conv1 + ELU (implicit, fp16 1-term W) -> h16 image
    cgemm<1><<<dim3(HWF/256, 1, BT), 256, CGEMM_SMEM>>>(
        w116, y16, nullptr, h16, b1);

    // conv2 + ELU (implicit) -> out fp32 NCHW
    cgemm<0><<<dim3(HWF/256, 1, BT), 256, CGEMM_SMEM>>>(
        w216, h16, out, nullptr, b2);
}

// round 14
// speedup vs baseline: 1.2747x; 1.0209x over previous
#include <cuda_runtime.h>
#include <cuda_bf16.h>
#include <cuda_fp16.h>
#include <math.h>
#include <stdint.h>

#define BT 2
#define CC 128
#define HH 128
#define WW 128
#define HS 64
#define NP 4096
#define K1 1152
#define HWF 16384
#define SCALEF 10.0f
#define SEL_THR 1e-7f
#define SLOTS 16
#define KMAX 128

// ===================== scratch =====================
__device__ __align__(256) __nv_bfloat16 g_bh [(size_t)BT*NP*CC];
__device__ __align__(256) __nv_bfloat16 g_bl [(size_t)BT*NP*CC];
__device__ __align__(256) __nv_bfloat16 g_fh [(size_t)BT*NP*CC];
__device__ __align__(256) __nv_bfloat16 g_fl [(size_t)BT*NP*CC];
__device__ __align__(256) __half        g_bgcl[(size_t)BT*HWF*CC]; // bg channels-last fp16
__device__ __align__(256) __half        g_y16 [(size_t)BT*HWF*CC]; // y image channels-last
__device__ __align__(256) __half        g_h16 [(size_t)BT*HWF*CC]; // h image channels-last
__device__ __align__(256) __half        g_w116[CC*K1];
__device__ __align__(256) __half        g_w216[CC*K1];
__device__ __align__(256) float g_bufA[(size_t)BT*NP*NP];
__device__ __align__(256) float g_bufB[(size_t)BT*NP*NP];
__device__ int   g_cidx[(size_t)BT*NP*32*SLOTS];
__device__ float g_cwgt[(size_t)BT*NP*32*SLOTS];
__device__ int   g_ccnt[BT*NP*32];
__device__ int   g_midx[(size_t)BT*NP*KMAX];
__device__ float g_mwgt[(size_t)BT*NP*KMAX];
__device__ int   g_mcnt[BT*NP];
__device__ float g_eq  [NP];
__device__ float g_ss  [BT*NP];
__device__ float g_inv [BT*NP];
__device__ float g_pmax[BT*32*NP];
__device__ float g_psum[BT*32*NP];
__device__ float g_cmax[BT*NP];
__device__ float g_csum[BT*NP];
__device__ float g_lthr[BT*NP];

__device__ __forceinline__ void split_store(__nv_bfloat16* H, __nv_bfloat16* L,
                                            size_t idx, float v) {
    __nv_bfloat16 h = __float2bfloat16(v);
    H[idx] = h;
    L[idx] = __float2bfloat16(v - __bfloat162float(h));
}
__device__ __forceinline__ uint32_t smem_u32(const void* p) {
    uint32_t a;
    asm("{ .reg .u64 t; cvta.to.shared.u64 t, %1; cvt.u32.u64 %0, t; }" : "=r"(a) : "l"(p));
    return a;
}
__device__ __forceinline__ void ldsm_x4(uint32_t (&r)[4], uint32_t addr) {
    asm volatile("ldmatrix.sync.aligned.m8n8.x4.shared.b16 {%0,%1,%2,%3}, [%4];"
                 : "=r"(r[0]), "=r"(r[1]), "=r"(r[2]), "=r"(r[3]) : "r"(addr));
}
__device__ __forceinline__ void mma_bf16(float (&d)[4], const uint32_t (&a)[4],
                                         uint32_t b0, uint32_t b1) {
    asm volatile("mma.sync.aligned.m16n8k16.row.col.f32.bf16.bf16.f32 "
        "{%0,%1,%2,%3}, {%4,%5,%6,%7}, {%8,%9}, {%0,%1,%2,%3};"
        : "+f"(d[0]), "+f"(d[1]), "+f"(d[2]), "+f"(d[3])
        : "r"(a[0]), "r"(a[1]), "r"(a[2]), "r"(a[3]), "r"(b0), "r"(b1));
}
__device__ __forceinline__ void mma_f16(float (&d)[4], const uint32_t (&a)[4],
                                        uint32_t b0, uint32_t b1) {
    asm volatile("mma.sync.aligned.m16n8k16.row.col.f32.f16.f16.f32 "
        "{%0,%1,%2,%3}, {%4,%5,%6,%7}, {%8,%9}, {%0,%1,%2,%3};"
        : "+f"(d[0]), "+f"(d[1]), "+f"(d[2]), "+f"(d[3])
        : "r"(a[0]), "r"(a[1]), "r"(a[2]), "r"(a[3]), "r"(b0), "r"(b1));
}
__device__ __forceinline__ void cpasync16(uint32_t saddr, const void* g) {
    asm volatile("cp.async.cg.shared.global [%0], [%1], 16;" :: "r"(saddr), "l"(g));
}
__device__ __forceinline__ void cpasync16z(uint32_t saddr, const void* g, int szbytes) {
    asm volatile("cp.async.cg.shared.global [%0], [%1], 16, %2;"
                 :: "r"(saddr), "l"(g), "r"(szbytes));
}

// ===================== prep =====================
__global__ void k_half(const float* __restrict__ src, __nv_bfloat16* H, __nv_bfloat16* L) {
    int idx = blockIdx.x * blockDim.x + threadIdx.x;
    if (idx >= BT * NP * CC) return;
    int c = idx & 127;
    int t = idx >> 7;
    int n = t & 4095;
    int b = t >> 12;
    int y = n >> 6, x = n & 63;
    float v = src[(((size_t)b*CC + c)*HH + 2*y)*WW + 2*x];
    split_store(H, L, (size_t)idx, v);
}

__global__ void k_ss() {
    int idx = blockIdx.x * blockDim.x + threadIdx.x;
    if (idx >= BT * NP) return;
    const __nv_bfloat162* h2 = (const __nv_bfloat162*)(g_bh + (size_t)idx * CC);
    const __nv_bfloat162* l2 = (const __nv_bfloat162*)(g_bl + (size_t)idx * CC);
    float s = 0.f;
#pragma unroll
    for (int c = 0; c < CC/2; c++) {
        float2 a = __bfloat1622float2(h2[c]);
        float2 bb = __bfloat1622float2(l2[c]);
        float v0 = a.x + bb.x, v1 = a.y + bb.y;
        s += v0*v0 + v1*v1;
    }
    g_ss[idx] = s;
}

__global__ void k_inv() {
    int idx = blockIdx.x * blockDim.x + threadIdx.x;
    if (idx >= BT * NP) return;
    int b = idx >> 12, n = idx & 4095;
    int ny = n >> 6, nx = n & 63;
    float s = 0.f;
#pragma unroll
    for (int i = 0; i < 3; i++)
#pragma unroll
        for (int j = 0; j < 3; j++) {
            int y = ny + i - 1, x = nx + j - 1;
            if ((unsigned)y < 64u && (unsigned)x < 64u)
                s += g_ss[b*NP + y*64 + x];
        }
    g_inv[idx] = 1.f / fmaxf(sqrtf(s), 1e-4f);
}

__global__ void k_bgcl(const float* __restrict__ bg) {
    __shared__ float tile[32][33];
    int b = blockIdx.z;
    int c0 = blockIdx.y * 32;
    int p0 = blockIdx.x * 32;
    int tx = threadIdx.x & 31, ty = threadIdx.x >> 5;
#pragma unroll
    for (int k = 0; k < 4; k++) {
        int c = c0 + ty + k*8;
        tile[ty + k*8][tx] = bg[((size_t)(b*CC + c))*HWF + p0 + tx];
    }
    __syncthreads();
#pragma unroll
    for (int k = 0; k < 4; k++) {
        int p = p0 + ty + k*8;
        g_bgcl[((size_t)(b*HWF + p))*CC + c0 + tx] = __float2half(tile[tx][ty + k*8]);
    }
}

__global__ void k_eq(const float* __restrict__ mask) {
    int n = blockIdx.x * blockDim.x + threadIdx.x;
    if (n >= NP) return;
    int ny = n / HS, nx = n % HS;
    float s = 0.f;
#pragma unroll
    for (int i = 0; i < 3; i++)
#pragma unroll
        for (int j = 0; j < 3; j++) {
            int y = ny + i - 1, x = nx + j - 1;
            if ((unsigned)y < HS && (unsigned)x < HS)
                s += mask[(2*y)*WW + 2*x];
        }
    g_eq[n] = ((s / 9.f) == 0.f) ? 1.f : 0.f;
}

// weight reorder: out[r][tap*128+c] = w[r][c*9+tap], single fp16
__global__ void k_wreorder(const float* __restrict__ w, __half* H) {
    int idx = blockIdx.x * blockDim.x + threadIdx.x;
    if (idx >= CC * K1) return;
    int r = idx / K1;
    int rem = idx % K1;
    int tap = rem >> 7;
    int c = rem & 127;
    H[idx] = __float2half(w[r * K1 + c * 9 + tap]);
}

// ===================== bf16-split GEMM1: 128m x 256n, 3-term ================
#define KT 32
#define STAGES 3
#define M2STAGE (8192*2 + 16384*2)     // Ah,Al 8KB + Bh,Bl 16KB = 48KB
#define M2SMEM (STAGES*M2STAGE)        // 147456

__global__ void __launch_bounds__(256, 1) mgemm256(
    const __nv_bfloat16* __restrict__ Ah, const __nv_bfloat16* __restrict__ Al,
    const __nv_bfloat16* __restrict__ Bh, const __nv_bfloat16* __restrict__ Bl,
    float* __restrict__ C, int K, int N,
    size_t sA, size_t sB, size_t sC)
{
    extern __shared__ char sm[];
    const uint32_t smb = smem_u32(sm);
    const int tid = threadIdx.x;
    const int bz = blockIdx.z;
    const int bm = blockIdx.y * 128;
    const int bn = blockIdx.x * 256;
    C += sC * bz;
    const __nv_bfloat16* ah = Ah + sA * bz;
    const __nv_bfloat16* al = Al + sA * bz;
    const __nv_bfloat16* bhp = Bh + sB * bz;
    const __nv_bfloat16* blp = Bl + sB * bz;

    const int NC = K >> 5;

    auto load_stage = [&](int s, int kc) {
        // A hi/lo: 128 rows x 32 cols = 512 16B chunks each
#pragma unroll
        for (int it = 0; it < 2; it++) {
            int id = tid + it * 256;
            int row = id >> 2, ch = id & 3;
            uint32_t swz = (uint32_t)(row * 64 + ((ch ^ ((row >> 1) & 3)) << 4));
            cpasync16(smb + s*M2STAGE + swz,        ah + (size_t)(bm + row) * K + kc + ch * 8);
            cpasync16(smb + s*M2STAGE + 8192 + swz, al + (size_t)(bm + row) * K + kc + ch * 8);
        }
        // B hi/lo: 256 rows x 32 cols = 1024 16B chunks each
#pragma unroll
        for (int it = 0; it < 4; it++) {
            int id = tid + it * 256;
            int row = id >> 2, ch = id & 3;
            uint32_t swz = (uint32_t)(row * 64 + ((ch ^ ((row >> 1) & 3)) << 4));
            cpasync16(smb + s*M2STAGE + 16384 + swz, bhp + (size_t)(bn + row) * K + kc + ch * 8);
            cpasync16(smb + s*M2STAGE + 32768 + swz, blp + (size_t)(bn + row) * K + kc + ch * 8);
        }
        asm volatile("cp.async.commit_group;");
    };

#pragma unroll
    for (int s = 0; s < STAGES - 1; s++) load_stage(s, s * KT);

    const int wid = tid >> 5, lane = tid & 31;
    const int wm = wid & 1, wn = wid >> 1;

    float acc[4][8][4];
#pragma unroll
    for (int a = 0; a < 4; a++)
#pragma unroll
        for (int bb = 0; bb < 8; bb++)
#pragma unroll
            for (int c = 0; c < 4; c++) acc[a][bb][c] = 0.f;

    for (int i = 0; i < NC; i++) {
        asm volatile("cp.async.wait_group 1;");
        __syncthreads();

        if (i + STAGES - 1 < NC)
            load_stage((i + STAGES - 1) % STAGES, (i + STAGES - 1) * KT);
        else
            asm volatile("cp.async.commit_group;");

        const uint32_t stb = smb + (i % STAGES) * M2STAGE;
#pragma unroll
        for (int h = 0; h < 2; h++) {
            uint32_t ar[4][4], alr[4][4];
            uint32_t bh2[8][2], bl2[8][2];
#pragma unroll
            for (int tm = 0; tm < 4; tm++) {
                int row = wm*64 + tm*16 + (lane & 15);
                int ch  = 2*h + (lane >> 4);
                uint32_t ad = stb + row*64 + ((ch ^ ((row >> 1) & 3)) << 4);
                ldsm_x4(ar[tm], ad);
                ldsm_x4(alr[tm], ad + 8192);
            }
#pragma unroll
            for (int tb = 0; tb < 4; tb++) {
                int row = wn*64 + tb*16 + ((lane >> 4) << 3) + (lane & 7);
                int ch  = 2*h + ((lane >> 3) & 1);
                uint32_t bd = stb + 16384 + row*64 + ((ch ^ ((row >> 1) & 3)) << 4);
                uint32_t r[4];
                ldsm_x4(r, bd);
                bh2[tb*2][0] = r[0]; bh2[tb*2][1] = r[1];
                bh2[tb*2+1][0] = r[2]; bh2[tb*2+1][1] = r[3];
                ldsm_x4(r, bd + 16384);
                bl2[tb*2][0] = r[0]; bl2[tb*2][1] = r[1];
                bl2[tb*2+1][0] = r[2]; bl2[tb*2+1][1] = r[3];
            }
#pragma unroll
            for (int tm = 0; tm < 4; tm++)
#pragma unroll
                for (int tn = 0; tn < 8; tn++) {
                    mma_bf16(acc[tm][tn], ar[tm], bh2[tn][0], bh2[tn][1]);
                    mma_bf16(acc[tm][tn], ar[tm], bl2[tn][0], bl2[tn][1]);
                    mma_bf16(acc[tm][tn], alr[tm], bh2[tn][0], bh2[tn][1]);
                }
        }
    }

#pragma unroll
    for (int tm = 0; tm < 4; tm++) {
        int row = bm + wm*64 + tm*16 + (lane >> 2);
#pragma unroll
        for (int hf = 0; hf < 2; hf++) {
            int r = row + hf*8;
            float* dst = C + (size_t)r * N + bn + wn*64 + (lane & 3)*2;
#pragma unroll
            for (int tn = 0; tn < 8; tn++)
                *(float2*)(dst + tn*8) = make_float2(acc[tm][tn][hf*2+0], acc[tm][tn][hf*2+1]);
        }
    }
}

// ===================== implicit conv GEMM: 128ch x 256pix, fp16 1-term W =====
#define CSTAGE (8192 + 16384)
#define CGEMM_SMEM (STAGES*CSTAGE)
#define TPITCH 136

template<int OUT16>
__global__ void __launch_bounds__(256, 1) cgemm(
    const __half* __restrict__ Wh,
    const __half* __restrict__ img,
    float* __restrict__ Cout, __half* __restrict__ out16,
    const float* __restrict__ bias)
{
    extern __shared__ char sm[];
    const uint32_t smb = smem_u32(sm);
    const int tid = threadIdx.x;
    const int bz = blockIdx.z;
    const int bn = blockIdx.x * 256;
    const __half* ib = img + (size_t)bz * HWF * CC;

    const int NC = K1 >> 5;   // 36

    auto load_stage = [&](int s, int kc) {
#pragma unroll
        for (int it = 0; it < 2; it++) {
            int id = tid + it * 256;
            int row = id >> 2, ch = id & 3;
            uint32_t swz = (uint32_t)(row * 64 + ((ch ^ ((row >> 1) & 3)) << 4));
            cpasync16(smb + s*CSTAGE + swz, Wh + (size_t)row * K1 + kc + ch * 8);
        }
        int tap = kc >> 7;
        int ki = tap / 3, kj = tap - ki * 3;
        int c0 = kc & 127;
#pragma unroll
        for (int it = 0; it < 4; it++) {
            int id = tid + it * 256;
            int row = id >> 2, ch = id & 3;
            int p = bn + row;
            int Y = (p >> 7) + ki - 1, X = (p & 127) + kj - 1;
            bool ok = (unsigned)Y < HH && (unsigned)X < WW;
            const __half* g = ok ? ib + ((size_t)(Y * WW + X)) * CC + c0 + ch * 8 : ib;
            uint32_t swz = (uint32_t)(row * 64 + ((ch ^ ((row >> 1) & 3)) << 4));
            cpasync16z(smb + s*CSTAGE + 8192 + swz, g, ok ? 16 : 0);
        }
        asm volatile("cp.async.commit_group;");
    };

#pragma unroll
    for (int s = 0; s < STAGES - 1; s++) load_stage(s, s * KT);

    const int wid = tid >> 5, lane = tid & 31;
    const int wm = wid & 1, wn = wid >> 1;

    float acc[4][8][4];
#pragma unroll
    for (int a = 0; a < 4; a++)
#pragma unroll
        for (int bb = 0; bb < 8; bb++)
#pragma unroll
            for (int c = 0; c < 4; c++) acc[a][bb][c] = 0.f;

    for (int i = 0; i < NC; i++) {
        asm volatile("cp.async.wait_group 1;");
        __syncthreads();

        if (i + STAGES - 1 < NC)
            load_stage((i + STAGES - 1) % STAGES, (i + STAGES - 1) * KT);
        else
            asm volatile("cp.async.commit_group;");

        const uint32_t stb = smb + (i % STAGES) * CSTAGE;
#pragma unroll
        for (int h = 0; h < 2; h++) {
            uint32_t ah[4][4];
            uint32_t bf[8][2];
#pragma unroll
            for (int tm = 0; tm < 4; tm++) {
                int row = wm*64 + tm*16 + (lane & 15);
                int ch  = 2*h + (lane >> 4);
                uint32_t ad = stb + row*64 + ((ch ^ ((row >> 1) & 3)) << 4);
                ldsm_x4(ah[tm], ad);
            }
#pragma unroll
            for (int tb = 0; tb < 4; tb++) {
                int row = wn*64 + tb*16 + ((lane >> 4) << 3) + (lane & 7);
                int ch  = 2*h + ((lane >> 3) & 1);
                uint32_t bd = stb + 8192 + row*64 + ((ch ^ ((row >> 1) & 3)) << 4);
                uint32_t r[4];
                ldsm_x4(r, bd);
                bf[tb*2][0] = r[0]; bf[tb*2][1] = r[1];
                bf[tb*2+1][0] = r[2]; bf[tb*2+1][1] = r[3];
            }
#pragma unroll
            for (int tm = 0; tm < 4; tm++)
#pragma unroll
                for (int tn = 0; tn < 8; tn++)
                    mma_f16(acc[tm][tn], ah[tm], bf[tn][0], bf[tn][1]);
        }
    }

    if (OUT16) {
        asm volatile("cp.async.wait_group 0;");
        __syncthreads();
        __half* st = (__half*)sm;
#pragma unroll
        for (int tm = 0; tm < 4; tm++) {
#pragma unroll
            for (int hf = 0; hf < 2; hf++) {
                int r = wm*64 + tm*16 + (lane >> 2) + hf*8;
                float bv = bias[r];
#pragma unroll
                for (int tn = 0; tn < 8; tn++) {
                    int col = wn*64 + tn*8 + (lane & 3)*2;
                    float x0 = acc[tm][tn][hf*2+0] + bv;
                    float x1 = acc[tm][tn][hf*2+1] + bv;
                    x0 = x0 > 0.f ? x0 : expf(x0) - 1.f;
                    x1 = x1 > 0.f ? x1 : expf(x1) - 1.f;
                    st[(size_t)col * TPITCH + r]       = __float2half(x0);
                    st[(size_t)(col+1) * TPITCH + r]   = __float2half(x1);
                }
            }
        }
        __syncthreads();
        __half* dst = out16 + ((size_t)bz * HWF + bn + tid) * CC;
        const uint4* srcv = (const uint4*)(st + (size_t)tid * TPITCH);
#pragma unroll
        for (int i = 0; i < 16; i++)
            ((uint4*)dst)[i] = srcv[i];
    } else {
        float* C = Cout + (size_t)bz * CC * HWF;
#pragma unroll
        for (int tm = 0; tm < 4; tm++) {
            int row = wm*64 + tm*16 + (lane >> 2);
#pragma unroll
            for (int hf = 0; hf < 2; hf++) {
                int r = row + hf*8;
                float bv = bias[r];
                float* dst = C + (size_t)r * HWF + bn + wn*64 + (lane & 3)*2;
#pragma unroll
                for (int tn = 0; tn < 8; tn++) {
                    float x0 = acc[tm][tn][hf*2+0] + bv;
                    float x1 = acc[tm][tn][hf*2+1] + bv;
                    x0 = x0 > 0.f ? x0 : expf(x0) - 1.f;
                    x1 = x1 > 0.f ? x1 : expf(x1) - 1.f;
                    *(float2*)(dst + tn*8) = make_float2(x0, x1);
                }
            }
        }
    }
}

// ===================== stencil =====================
__global__ void __launch_bounds__(256) k_stencil9(const float* __restrict__ G,
                                                  float* __restrict__ out) {
    __shared__ float t3[3][64][64];
    int bid = blockIdx.x;
    int b = bid >> 12;
    int rest = bid & 4095;
    int ny = rest >> 6, py = rest & 63;
    const float* Gb = G + (size_t)b * NP * NP;
    float* ob = out + (size_t)b * NP * NP;
    int tid = threadIdx.x;

#pragma unroll
    for (int dy = 0; dy < 3; dy++) {
        int gy = ny + dy - 1, gpy = py + dy - 1;
        bool ok = (unsigned)gy < 64 && (unsigned)gpy < 64;
        for (int idx = tid; idx < 4096; idx += 256) {
            int i = idx >> 6, jj = idx & 63;
            t3[dy][i][jj] = ok ? Gb[((size_t)(gy*64 + i)) * NP + gpy*64 + jj] : 0.f;
        }
    }
    __syncthreads();

    int px = tid & 63;
    int nx0 = tid >> 6;
    for (int nx = nx0; nx < 64; nx += 4) {
        float s = 0.f;
#pragma unroll
        for (int dy = 0; dy < 3; dy++)
#pragma unroll
            for (int dx = -1; dx <= 1; dx++) {
                int a = nx + dx, c = px + dx;
                if ((unsigned)a < 64 && (unsigned)c < 64)
                    s += t3[dy][a][c];
            }
        ob[((size_t)(ny*64 + nx)) * NP + py*64 + px] = s * g_inv[b*NP + ny*64 + nx];
    }
}

// ===================== fuse1 + permutation =====================
__global__ void k_fuseperm(const float* __restrict__ in, float* __restrict__ out) {
    __shared__ float tile[64 * 65];
    int brow = blockIdx.x;
    int b = brow / NP, rp = brow % NP;
    int nx = rp >> 6, ny = rp & 63;
    int r = ny * 64 + nx;
    const float* src = in + (size_t)b * NP * NP;
    float*       dst = out + ((size_t)b * NP + rp) * NP;
    int tid = threadIdx.x;
    for (int k = tid; k < NP; k += 256) {
        float f = src[(size_t)r * NP + k];
        if (r > 0 && k > 0)           f += src[(size_t)(r-1) * NP + k - 1];
        if (r < NP-1 && k < NP-1)     f += src[(size_t)(r+1) * NP + k + 1];
        tile[(k & 63) * 65 + (k >> 6)] = f;
    }
    __syncthreads();
    for (int j = tid; j < NP; j += 256)
        dst[j] = tile[(j >> 6) * 65 + (j & 63)];
}

// ===================== softmax stats (fuse2 on the fly) =====================
__global__ void k_smax1(const float* __restrict__ in) {
    int col = blockIdx.x * 256 + threadIdx.x;
    int chunk = blockIdx.y;
    int b = blockIdx.z;
    int lane = threadIdx.x & 31;
    const float* base = in + (size_t)b * NP * NP;
    int r0 = chunk * 128;

    float pm1 = (r0 > 0) ? base[(size_t)(r0-1) * NP + col] : 0.f;
    float p0  = base[(size_t)r0 * NP + col];
    float pp1 = (r0 + 1 < NP) ? base[(size_t)(r0+1) * NP + col] : 0.f;

    float mx = -1e30f, sm = 0.f;
    for (int r = r0; r < r0 + 128; r++) {
        float um1 = __shfl_up_sync(0xffffffffu, pm1, 1);
        if (lane == 0)
            um1 = (r > 0 && col > 0) ? base[(size_t)(r-1) * NP + col - 1] : 0.f;
        float dp1 = __shfl_down_sync(0xffffffffu, pp1, 1);
        if (lane == 31)
            dp1 = (r < NP-1 && col < NP-1) ? base[(size_t)(r+1) * NP + col + 1] : 0.f;
        float v = p0 + um1 + dp1;
        float l = v * (g_eq[r] * SCALEF);
        if (l > mx) { sm = sm * expf(mx - l) + 1.f; mx = l; }
        else        { sm += expf(l - mx); }
        pm1 = p0; p0 = pp1;
        pp1 = (r + 2 < NP) ? base[(size_t)(r+2) * NP + col] : 0.f;
    }
    g_pmax[((size_t)b * 32 + chunk) * NP + col] = mx;
    g_psum[((size_t)b * 32 + chunk) * NP + col] = sm;
}

__global__ void k_smax2() {
    int idx = blockIdx.x * blockDim.x + threadIdx.x;
    if (idx >= BT * NP) return;
    int b = idx / NP, col = idx % NP;
    float M = -1e30f;
    for (int i = 0; i < 32; i++)
        M = fmaxf(M, g_pmax[((size_t)b * 32 + i) * NP + col]);
    float S = 0.f;
    for (int i = 0; i < 32; i++)
        S += g_psum[((size_t)b * 32 + i) * NP + col] *
             expf(g_pmax[((size_t)b * 32 + i) * NP + col] - M);
    g_cmax[idx] = M;
    g_csum[idx] = S;
    g_lthr[idx] = M + logf(SEL_THR * S);
}

// ===================== sparse selection (R10 exact) =========================
__global__ void k_sel(const float* __restrict__ in) {
    int col = blockIdx.x * 256 + threadIdx.x;    // p
    int chunk = blockIdx.y;
    int b = blockIdx.z;
    int lane = threadIdx.x & 31;
    const float* base = in + (size_t)b * NP * NP;
    int r0 = chunk * 128;

    float lth = g_lthr[b*NP + col];
    float M   = g_cmax[b*NP + col];
    float Sin = 1.f / g_csum[b*NP + col];

    float pm1 = (r0 > 0) ? base[(size_t)(r0-1) * NP + col] : 0.f;
    float p0  = base[(size_t)r0 * NP + col];
    float pp1 = (r0 + 1 < NP) ? base[(size_t)(r0+1) * NP + col] : 0.f;

    int s = 0;
    size_t slotbase = (((size_t)(b*NP + col)) * 32 + chunk) * SLOTS;
    for (int r = r0; r < r0 + 128; r++) {
        float um1 = __shfl_up_sync(0xffffffffu, pm1, 1);
        if (lane == 0)
            um1 = (r > 0 && col > 0) ? base[(size_t)(r-1) * NP + col - 1] : 0.f;
        float dp1 = __shfl_down_sync(0xffffffffu, pp1, 1);
        if (lane == 31)
            dp1 = (r < NP-1 && col < NP-1) ? base[(size_t)(r+1) * NP + col + 1] : 0.f;
        float v = p0 + um1 + dp1;
        float eqv = g_eq[r];
        float l = v * (eqv * SCALEF);
        if (l > lth && eqv != 0.f && s < SLOTS) {
            g_cidx[slotbase + s] = r;
            g_cwgt[slotbase + s] = expf(l - M) * Sin * eqv;
            s++;
        }
        pm1 = p0; p0 = pp1;
        pp1 = (r + 2 < NP) ? base[(size_t)(r+2) * NP + col] : 0.f;
    }
    g_ccnt[(b*NP + col) * 32 + chunk] = s;
}

__global__ void k_merge() {
    int idx = blockIdx.x * blockDim.x + threadIdx.x;
    if (idx >= BT * NP) return;
    int cnt = 0;
    size_t ob = (size_t)idx * KMAX;
    for (int ch = 0; ch < 32; ch++) {
        int c = g_ccnt[idx * 32 + ch];
        size_t sb = (((size_t)idx) * 32 + ch) * SLOTS;
        for (int i = 0; i < c && cnt < KMAX; i++) {
            g_midx[ob + cnt] = g_cidx[sb + i];
            g_mwgt[ob + cnt] = g_cwgt[sb + i];
            cnt++;
        }
    }
    g_mcnt[idx] = cnt;
}

// ===================== sparse apply + transposed-conv gather ================
__global__ void k_apply() {
    int wid = threadIdx.x >> 5, lane = threadIdx.x & 31;
    int P = blockIdx.x * 8 + wid;
    int b = blockIdx.y;
    int Y = P >> 7, X = P & 127;
    const __half* bgc = g_bgcl + (size_t)b * HWF * CC;
    float4 acc = make_float4(0.f, 0.f, 0.f, 0.f);
#pragma unroll
    for (int di = 0; di < 4; di++) {
        int ty = Y + 1 - di;
        if (ty < 0 || (ty & 1)) continue;
        int my = ty >> 1;
        if (my >= HS) continue;
#pragma unroll
        for (int dj = 0; dj < 4; dj++) {
            int tx = X + 1 - dj;
            if (tx < 0 || (tx & 1)) continue;
            int mx = tx >> 1;
            if (mx >= HS) continue;
            int p = my * 64 + mx;
            int lb = b * NP + p;
            int cnt = g_mcnt[lb];
            const int*   il = g_midx + (size_t)lb * KMAX;
            const float* wl = g_mwgt + (size_t)lb * KMAX;
            for (int i = 0; i < cnt; i++) {
                int m = il[i];
                float w = wl[i];
                int miy = m >> 6, mix = m & 63;
                int Ys = 2*miy + di - 1, Xs = 2*mix + dj - 1;
                if ((unsigned)Ys >= HH || (unsigned)Xs >= WW) continue;
                union { uint2 u; __half2 h[2]; } v;
                v.u = *(const uint2*)(bgc + ((size_t)(Ys * WW + Xs)) * CC + lane * 4);
                float2 a0 = __half22float2(v.h[0]);
                float2 a1 = __half22float2(v.h[1]);
                acc.x += w * a0.x; acc.y += w * a0.y;
                acc.z += w * a1.x; acc.w += w * a1.y;
            }
        }
    }
    union { __half2 h[2]; uint2 u; } cv;
    cv.h[0] = __floats2half2_rn(acc.x * 0.25f, acc.y * 0.25f);
    cv.h[1] = __floats2half2_rn(acc.z * 0.25f, acc.w * 0.25f);
    *(uint2*)(g_y16 + ((size_t)b * HWF + P) * CC + lane * 4) = cv.u;
}

// ===================== host orchestration =====================
extern "C" void kernel_launch(void* const* d_in, const int* in_sizes, int n_in,
                              void* d_out, int out_size) {
    const float* fg   = (const float*)d_in[0];
    const float* bg   = (const float*)d_in[1];
    const float* mask = (const float*)d_in[2];
    const float* w1   = (const float*)d_in[3];
    const float* b1   = (const float*)d_in[4];
    const float* w2   = (const float*)d_in[5];
    const float* b2   = (const float*)d_in[6];
    float* out = (float*)d_out;

    cudaFuncSetAttribute(mgemm256, cudaFuncAttributeMaxDynamicSharedMemorySize, M2SMEM);
    cudaFuncSetAttribute(cgemm<0>, cudaFuncAttributeMaxDynamicSharedMemorySize, CGEMM_SMEM);
    cudaFuncSetAttribute(cgemm<1>, cudaFuncAttributeMaxDynamicSharedMemorySize, CGEMM_SMEM);

    __nv_bfloat16 *bh, *bl, *fh, *fl;
    __half *y16, *h16, *w116, *w216;
    float *bufA, *bufB;
    cudaGetSymbolAddress((void**)&bh, g_bh);     cudaGetSymbolAddress((void**)&bl, g_bl);
    cudaGetSymbolAddress((void**)&fh, g_fh);     cudaGetSymbolAddress((void**)&fl, g_fl);
    cudaGetSymbolAddress((void**)&y16, g_y16);   cudaGetSymbolAddress((void**)&h16, g_h16);
    cudaGetSymbolAddress((void**)&w116, g_w116); cudaGetSymbolAddress((void**)&w216, g_w216);
    cudaGetSymbolAddress((void**)&bufA, g_bufA);
    cudaGetSymbolAddress((void**)&bufB, g_bufB);

    // prep
    k_half    <<<(BT*NP*CC + 255)/256, 256>>>(bg, bh, bl);
    k_half    <<<(BT*NP*CC + 255)/256, 256>>>(fg, fh, fl);
    k_ss      <<<(BT*NP + 255)/256, 256>>>();
    k_inv     <<<(BT*NP + 255)/256, 256>>>();
    k_bgcl    <<<dim3(HWF/32, CC/32, BT), 256>>>(bg);
    k_eq      <<<16, 256>>>(mask);
    k_wreorder<<<(CC*K1 + 255)/256, 256>>>(w1, w116);
    k_wreorder<<<(CC*K1 + 255)/256, 256>>>(w2, w216);

    // GEMM1: G[u][v] = sum_c b[u][c] f[v][c]  (bf16 3-term, 128x256) -> bufA
    mgemm256<<<dim3(16, 32, BT), 256, M2SMEM>>>(
        bh, bl, fh, fl, bufA, CC, NP,
        (size_t)NP * CC, (size_t)NP * CC, (size_t)NP * NP);

    // scores = 9-tap diagonal stencil / norm -> bufB
    k_stencil9<<<BT * 4096, 256>>>(bufA, bufB);

    // fuse1 + permutation -> bufA
    k_fuseperm<<<BT * NP, 256>>>(bufB, bufA);

    // fuse2 on-the-fly + softmax stats
    k_smax1<<<dim3(16, 32, BT), 256>>>(bufA);
    k_smax2<<<32, 256>>>();

    // sparse selection + merge
    k_sel  <<<dim3(16, 32, BT), 256>>>(bufA);
    k_merge<<<32, 256>>>();

    // sparse attention apply + transposed-conv gather -> y16
    k_apply<<<dim3(HWF/8, BT), 256>>>();

    // conv1 + ELU (implicit, fp16 1-term W) -> h16 image
    cgemm<1><<<dim3(HWF/256, 1, BT), 256, CGEMM_SMEM>>>(
        w116, y16, nullptr, h16, b1);

    // conv2 + ELU (implicit) -> out fp32 NCHW
    cgemm<0><<<dim3(HWF/256, 1, BT), 256, CGEMM_SMEM>>>(
        w216, h16, out, nullptr, b2);
}